// round 14
// baseline (speedup 1.0000x reference)
#include <cuda_runtime.h>
#include <cuda_bf16.h>
#include <cstdint>
#include <cstddef>

#define MUL 128
#define TOT 1152
#define NM  384
#define MAXN 4096
#define MAXE 65536
#define S128 0.08838834764831845f
#define IS3  0.57735026918962576f
#define IS5  0.44721359549995794f

// ---------------- scratch ----------------
__device__ float g_na0[MAXN * TOT];
__device__ float g_na [MAXN * TOT];
__device__ float g_xp [MAXN * TOT];
__device__ float g_nf [MAXN * NM];
__device__ float g_nh [MAXN * NM];
__device__ float g_ng [MAXN * NM];
__device__ float g_we [(size_t)MAXE * MUL];
__device__ float g_h  [(size_t)MAXE * NM];
__device__ float g_w  [(size_t)MAXE * MUL];
__device__ float g_np [(size_t)MAXE * TOT];
__device__ float g_g  [(size_t)MAXE * NM];

#define BLK 8192
#define OFF_FCW1 0
#define OFF_FCW2 49152
#define OFF_NGW1 65536
#define OFF_NGW2 212992
#define OFF_WOUT 360448
#define OFF_WIN  409600
#define OFF_WN   458752
#define OFF_PW1  507904
#define OFF_PW2  655360
#define PW_TOTAL 802816
__device__ __nv_bfloat16 g_pw_hi[PW_TOTAL];
__device__ __nv_bfloat16 g_pw_lo[PW_TOTAL];

__device__ __forceinline__ uint32_t smem_to_u32(const void* p) {
    uint32_t a;
    asm("{ .reg .u64 t; cvta.to.shared.u64 t, %1; cvt.u32.u64 %0, t; }" : "=r"(a) : "l"(p));
    return a;
}
__device__ __forceinline__ float silu_f(float x) { return x / (1.0f + __expf(-x)); }
__device__ __forceinline__ float ssp_f(float x) {
    return fmaxf(x, 0.0f) + log1pf(__expf(-fabsf(x))) - 0.69314718055994531f;
}
__device__ __forceinline__ int sw_unit(int row, int u) {
    return row * 8 + (u ^ (row & 7));
}
__device__ __forceinline__ int merged_to_planar(int j) {
    if (j < 128) return j;
    if (j < 512) { int r = j - 128; int u = r / 3; int c = r - 3 * u; return (1 + c) * 128 + u; }
    int r = j - 512; int u = r / 5; int c = r - 5 * u; return (4 + c) * 128 + u;
}

__device__ __forceinline__ void ldmat_x4(uint32_t* r, uint32_t addr) {
    asm volatile("ldmatrix.sync.aligned.m8n8.x4.shared.b16 {%0,%1,%2,%3}, [%4];"
        : "=r"(r[0]), "=r"(r[1]), "=r"(r[2]), "=r"(r[3]) : "r"(addr));
}
__device__ __forceinline__ void mma_bf16(float* c, const uint32_t* a, uint32_t b0, uint32_t b1) {
    asm volatile("mma.sync.aligned.m16n8k16.row.col.f32.bf16.bf16.f32 "
        "{%0,%1,%2,%3}, {%4,%5,%6,%7}, {%8,%9}, {%0,%1,%2,%3};"
        : "+f"(c[0]), "+f"(c[1]), "+f"(c[2]), "+f"(c[3])
        : "r"(a[0]), "r"(a[1]), "r"(a[2]), "r"(a[3]), "r"(b0), "r"(b1));
}
__device__ __forceinline__ void cp_async16(uint32_t dst, const void* src) {
    asm volatile("cp.async.cg.shared.global [%0], [%1], 16;" :: "r"(dst), "l"(src));
}
#define CP_COMMIT() asm volatile("cp.async.commit_group;" ::: "memory")
#define CP_WAIT0()  asm volatile("cp.async.wait_group 0;" ::: "memory")

// ---------------- batched weight prep ----------------
__global__ void prep_all(
    const float* __restrict__ fcW1, const float* __restrict__ fcW2,
    const float* __restrict__ gW1,  const float* __restrict__ gW2,
    const float* __restrict__ pW1,  const float* __restrict__ pW2,
    const float* __restrict__ Wout, const float* __restrict__ Win,
    const float* __restrict__ Wn)
{
    int job = blockIdx.y;
    const float* W;
    int K, Nn, off;
    switch (job) {
        case 0:  W = fcW1; K = NM;  Nn = MUL; off = OFF_FCW1; break;
        case 1:  W = fcW2; K = MUL; Nn = MUL; off = OFF_FCW2; break;
        case 2:  W = gW1;  K = NM;  Nn = NM;  off = OFF_NGW1; break;
        case 3:  W = gW2;  K = NM;  Nn = NM;  off = OFF_NGW2; break;
        case 4:  W = pW1;  K = NM;  Nn = NM;  off = OFF_PW1;  break;
        case 5:  W = pW2;  K = NM;  Nn = NM;  off = OFF_PW2;  break;
        default: {
            int grp = (job - 6) / 3;
            int i   = (job - 6) % 3;
            const float* base = (grp == 0) ? Wout : (grp == 1) ? Win : Wn;
            int boff = (grp == 0) ? OFF_WOUT : (grp == 1) ? OFF_WIN : OFF_WN;
            W = base + i * MUL * MUL; K = MUL; Nn = MUL; off = boff + i * 2 * BLK;
            break;
        }
    }
    int idx = blockIdx.x * blockDim.x + threadIdx.x;
    if (idx >= K * Nn) return;
    int kg = idx / Nn, ng = idx - kg * Nn;
    float x = W[idx];
    __nv_bfloat16 h = __float2bfloat16(x);
    __nv_bfloat16 l = __float2bfloat16(x - __bfloat162float(h));
    int kch = K >> 6;
    int nt = ng >> 7, n = ng & 127, kc = kg >> 6, k = kg & 63;
    int blk = nt * kch + kc;
    int e = blk * BLK + sw_unit(n, k >> 3) * 8 + (k & 7) + off;
    g_pw_hi[e] = h;
    g_pw_lo[e] = l;
}

// ---------------- elementwise kernels ----------------
__global__ void k_xplan(const float* __restrict__ na, int N) {
    int idx = blockIdx.x * blockDim.x + threadIdx.x;
    if (idx >= N * MUL) return;
    int n = idx >> 7, u = idx & 127;
    const float* x = na + (size_t)n * TOT;
    float v[9];
    v[0] = x[u];
    #pragma unroll
    for (int c = 0; c < 3; c++) v[1 + c] = x[128 + u * 3 + c];
    #pragma unroll
    for (int c = 0; c < 5; c++) v[4 + c] = x[512 + u * 5 + c];
    float* xp = g_xp + (size_t)n * TOT;
    #pragma unroll
    for (int p = 0; p < 9; p++) xp[p * 128 + u] = v[p];
    float* f = g_nf + (size_t)n * NM;
    f[u] = v[0];
    f[128 + u] = sqrtf(v[1] * v[1] + v[2] * v[2] + v[3] * v[3]);
    f[256 + u] = sqrtf(v[4] * v[4] + v[5] * v[5] + v[6] * v[6] + v[7] * v[7] + v[8] * v[8]);
}

__global__ void k_gate_node(int N) {
    int idx = blockIdx.x * blockDim.x + threadIdx.x;
    if (idx >= N * MUL) return;
    int n = idx >> 7, u = idx & 127;
    const float* g = g_ng + (size_t)n * NM;
    float* xp = g_xp + (size_t)n * TOT;
    float g1 = g[128 + u], g2 = g[256 + u];
    xp[u] = g[u];
    #pragma unroll
    for (int p = 1; p < 4; p++) xp[p * 128 + u] *= g1;
    #pragma unroll
    for (int p = 4; p < 9; p++) xp[p * 128 + u] *= g2;
}

__global__ void k_mtwe(const float* __restrict__ ea,
                       const float* __restrict__ W1, const float* __restrict__ W2, int E) {
    __shared__ float smt[2][8];
    int half = threadIdx.x >> 7;
    int t = threadIdx.x & 127;
    int e = blockIdx.x * 2 + half;
    int ec = (e < E) ? e : (E - 1);
    if (t < 8) {
        const float* a = ea + (size_t)ec * 64;
        float acc = 0.0f;
        #pragma unroll 16
        for (int i = 0; i < 64; i++) acc += a[i] * W1[i * 8 + t];
        smt[half][t] = ssp_f(acc * 0.125f);
    }
    __syncthreads();
    if (e < E) {
        float acc = 0.0f;
        #pragma unroll
        for (int j = 0; j < 8; j++) acc += smt[half][j] * W2[j * MUL + t];
        g_we[(size_t)e * MUL + t] = acc * 0.35355339059327373f;
    }
}

__global__ void k_out(const float* __restrict__ npa, float* __restrict__ out, int E) {
    int idx = blockIdx.x * blockDim.x + threadIdx.x;
    if (idx >= E * (TOT / 4)) return;
    int e = idx / (TOT / 4);
    int j4 = (idx - e * (TOT / 4)) * 4;
    const float* pl = g_np + (size_t)e * TOT;
    float4 npv = *(const float4*)(npa + (size_t)e * TOT + j4);
    float4 o;
    o.x = pl[merged_to_planar(j4)]     + npv.x;
    o.y = pl[merged_to_planar(j4 + 1)] + npv.y;
    o.z = pl[merged_to_planar(j4 + 2)] + npv.z;
    o.w = pl[merged_to_planar(j4 + 3)] + npv.w;
    *(float4*)(out + (size_t)e * TOT + j4) = o;
}

// ---------------- mma.sync GEMM: 64x128 tile, 3 CTAs/SM ----------------
#define GT 256
#define MT 64
#define SM_AHI 0
#define SM_ALO 8192
#define SM_BHI 16384
#define SM_BLO 32768
#define SM_IDX 49152
#define SM_TOTAL 49664

// mode_a: 0 plain; 1 G5 np recompute (plane=by); 2 planar plain (plane=by);
//         3 G1 s0 on the fly; 6 G3 f0' on the fly (mul=g_w)
// mode_ep: 0 +bias ; 1 silu(+bias) ; 2 (acc+bias)*mul ; 4 planar *S128 (+bias if plane0)
__global__ void __launch_bounds__(GT, 3) gemm_kernel(
    const float* __restrict__ A, int lda, int kchunks,
    const __nv_bfloat16* __restrict__ Bhi, const __nv_bfloat16* __restrict__ Blo,
    float* __restrict__ OUT, int ldo,
    const float* __restrict__ bias,
    const float* __restrict__ mul,
    const float* __restrict__ gate,
    const int* __restrict__ dstp, const int* __restrict__ srcp,
    int mode_a, int mode_ep, int E)
{
    extern __shared__ char smg[];
    uint32_t smb = smem_to_u32(smg);
    int* SIDX = (int*)(smg + SM_IDX);
    const int tid = threadIdx.x;
    const int wid = tid >> 5;
    const int lane = tid & 31;
    const int m0 = blockIdx.x * MT;
    const int by = blockIdx.y;
    const int plane = (mode_a == 1 || mode_a == 2) ? by : 0;
    const int ntb = (mode_a == 1 || mode_a == 2) ? 0 : by;

    const int wm0 = (wid & 1) * 32;
    const int wn0 = (wid >> 1) * 32;

    if (mode_a == 1 || mode_a == 3 || mode_a == 6) {
        if (tid < MT) {
            int e = m0 + tid; if (e >= E) e = E - 1;
            SIDX[tid] = dstp[e];
            SIDX[MT + tid] = srcp[e];
        }
        __syncthreads();
    }

    float acc[2][4][4];
    #pragma unroll
    for (int i = 0; i < 2; i++)
        #pragma unroll
        for (int j = 0; j < 4; j++)
            #pragma unroll
            for (int q = 0; q < 4; q++) acc[i][j][q] = 0.0f;

    int bsel = ntb;
    if (mode_a == 1 || mode_a == 2) bsel = (plane == 0) ? 0 : (plane < 4 ? 1 : 2);

    for (int kc = 0; kc < kchunks; kc++) {
        // B tile via cp.async.cg (overlaps A convert below)
        {
            int blk = bsel * kchunks + kc;
            const char* sH = (const char*)(Bhi + (size_t)blk * BLK);
            const char* sL = (const char*)(Blo + (size_t)blk * BLK);
            #pragma unroll
            for (int it = 0; it < 4; it++) {
                int i = tid + it * GT;
                cp_async16(smb + SM_BHI + i * 16, sH + i * 16);
                cp_async16(smb + SM_BLO + i * 16, sL + i * 16);
            }
            CP_COMMIT();
        }
        // A tile: 64 rows x 64 k = 512 units, 2 per thread
        #pragma unroll
        for (int it = 0; it < 2; it++) {
            int i = tid + it * GT;
            int r = i >> 3, u = i & 7;
            int e = m0 + r;
            int k0 = u * 8;
            float v[8];
            #pragma unroll
            for (int q = 0; q < 8; q++) v[q] = 0.0f;
            if (e < E) {
                if (mode_a == 0) {
                    const float* p = A + (size_t)e * lda + kc * 64 + k0;
                    float4 v0 = *(const float4*)(p);
                    float4 v1 = *(const float4*)(p + 4);
                    v[0]=v0.x; v[1]=v0.y; v[2]=v0.z; v[3]=v0.w;
                    v[4]=v1.x; v[5]=v1.y; v[6]=v1.z; v[7]=v1.w;
                } else if (mode_a == 2) {
                    const float* p = A + (size_t)e * lda + plane * 128 + kc * 64 + k0;
                    float4 v0 = *(const float4*)(p);
                    float4 v1 = *(const float4*)(p + 4);
                    v[0]=v0.x; v[1]=v0.y; v[2]=v0.z; v[3]=v0.w;
                    v[4]=v1.x; v[5]=v1.y; v[6]=v1.z; v[7]=v1.w;
                } else if (mode_a == 1) {
                    if (plane == 0) {
                        const float* p = gate + (size_t)e * NM + kc * 64 + k0;
                        float4 v0 = *(const float4*)(p);
                        float4 v1 = *(const float4*)(p + 4);
                        v[0]=v0.x; v[1]=v0.y; v[2]=v0.z; v[3]=v0.w;
                        v[4]=v1.x; v[5]=v1.y; v[6]=v1.z; v[7]=v1.w;
                    } else {
                        const float* nd = A + (size_t)SIDX[r] * TOT + plane * 128 + kc * 64 + k0;
                        const float* ns = A + (size_t)SIDX[MT + r] * TOT + plane * 128 + kc * 64 + k0;
                        int go = (plane < 4) ? 128 : 256;
                        const float* gp = gate + (size_t)e * NM + go + kc * 64 + k0;
                        const float* wr = mul + (size_t)e * MUL;
                        #pragma unroll
                        for (int q = 0; q < 8; q++) {
                            int k = kc * 64 + k0 + q;
                            int j = (plane < 4) ? (128 + k * 3 + (plane - 1))
                                                : (512 + k * 5 + (plane - 4));
                            v[q] = (nd[q] + ns[q]) * wr[j / 9] * gp[q];
                        }
                    }
                } else if (mode_a == 3) { // s0 from g_na0 gathers
                    const float* nd = A + (size_t)SIDX[r] * TOT;
                    const float* ns = A + (size_t)SIDX[MT + r] * TOT;
                    int kg = kc * 64 + k0;
                    if (kg < 128) {
                        #pragma unroll
                        for (int q = 0; q < 8; q++)
                            v[q] = 0.5f * (nd[kg + q] + ns[kg + q]);
                    } else if (kg < 256) {
                        int u0 = kg - 128;
                        #pragma unroll
                        for (int q = 0; q < 8; q++) {
                            int uu = u0 + q;
                            v[q] = (nd[128 + uu] * ns[128 + uu] + nd[256 + uu] * ns[256 + uu]
                                  + nd[384 + uu] * ns[384 + uu]) * IS3;
                        }
                    } else {
                        int u0 = kg - 256;
                        #pragma unroll
                        for (int q = 0; q < 8; q++) {
                            int uu = u0 + q;
                            v[q] = (nd[512 + uu] * ns[512 + uu] + nd[640 + uu] * ns[640 + uu]
                                  + nd[768 + uu] * ns[768 + uu] + nd[896 + uu] * ns[896 + uu]
                                  + nd[1024 + uu] * ns[1024 + uu]) * IS5;
                        }
                    }
                } else { // mode_a == 6: f0' from g_na gathers + g_w
                    const float* nd = A + (size_t)SIDX[r] * TOT;
                    const float* ns = A + (size_t)SIDX[MT + r] * TOT;
                    const float* wr = mul + (size_t)e * MUL;
                    int kg = kc * 64 + k0;
                    if (kg < 128) {
                        #pragma unroll
                        for (int q = 0; q < 8; q++) {
                            int uu = kg + q;
                            v[q] = (nd[uu] + ns[uu]) * wr[uu / 9];
                        }
                    } else if (kg < 256) {
                        int u0 = kg - 128;
                        #pragma unroll
                        for (int q = 0; q < 8; q++) {
                            int uu = u0 + q;
                            float s = 0.0f;
                            #pragma unroll
                            for (int p = 1; p < 4; p++) {
                                int j = 128 + uu * 3 + (p - 1);
                                float t = (nd[p * 128 + uu] + ns[p * 128 + uu]) * wr[j / 9];
                                s += t * t;
                            }
                            v[q] = sqrtf(s);
                        }
                    } else {
                        int u0 = kg - 256;
                        #pragma unroll
                        for (int q = 0; q < 8; q++) {
                            int uu = u0 + q;
                            float s = 0.0f;
                            #pragma unroll
                            for (int p = 4; p < 9; p++) {
                                int j = 512 + uu * 5 + (p - 4);
                                float t = (nd[p * 128 + uu] + ns[p * 128 + uu]) * wr[j / 9];
                                s += t * t;
                            }
                            v[q] = sqrtf(s);
                        }
                    }
                }
            }
            uint32_t hi[4], lo[4];
            #pragma unroll
            for (int q = 0; q < 4; q++) {
                __nv_bfloat16 h0 = __float2bfloat16(v[2*q]);
                __nv_bfloat16 h1 = __float2bfloat16(v[2*q+1]);
                __nv_bfloat16 l0 = __float2bfloat16(v[2*q]   - __bfloat162float(h0));
                __nv_bfloat16 l1 = __float2bfloat16(v[2*q+1] - __bfloat162float(h1));
                __nv_bfloat162 h2(h0, h1), l2(l0, l1);
                hi[q] = *(uint32_t*)&h2;
                lo[q] = *(uint32_t*)&l2;
            }
            int off = sw_unit(r, u) * 16;
            *(uint4*)(smg + SM_AHI + off) = make_uint4(hi[0], hi[1], hi[2], hi[3]);
            *(uint4*)(smg + SM_ALO + off) = make_uint4(lo[0], lo[1], lo[2], lo[3]);
        }
        CP_WAIT0();
        __syncthreads();

        // MMA with cross-pass fragment reuse (8 ldmatrix.x4 per ks)
        #pragma unroll
        for (int ks = 0; ks < 4; ks++) {
            const int ua = ks * 2 + (lane >> 4);
            const int ub = ks * 2 + ((lane >> 3) & 1);
            const int rowa0 = wm0 + (lane & 15);
            const int nb = wn0 + (lane >> 4) * 8 + (lane & 7);

            uint32_t aH[2][4];
            #pragma unroll
            for (int mt2 = 0; mt2 < 2; mt2++)
                ldmat_x4(aH[mt2], smb + SM_AHI + sw_unit(rowa0 + mt2 * 16, ua) * 16);
            uint32_t bH[2][4];
            #pragma unroll
            for (int nq = 0; nq < 2; nq++)
                ldmat_x4(bH[nq], smb + SM_BHI + sw_unit(nb + nq * 16, ub) * 16);
            #pragma unroll
            for (int mt2 = 0; mt2 < 2; mt2++)
                #pragma unroll
                for (int nt2 = 0; nt2 < 4; nt2++)
                    mma_bf16(acc[mt2][nt2], aH[mt2], bH[nt2 >> 1][(nt2 & 1) * 2],
                             bH[nt2 >> 1][(nt2 & 1) * 2 + 1]);
            {
                uint32_t aL[2][4];
                #pragma unroll
                for (int mt2 = 0; mt2 < 2; mt2++)
                    ldmat_x4(aL[mt2], smb + SM_ALO + sw_unit(rowa0 + mt2 * 16, ua) * 16);
                #pragma unroll
                for (int mt2 = 0; mt2 < 2; mt2++)
                    #pragma unroll
                    for (int nt2 = 0; nt2 < 4; nt2++)
                        mma_bf16(acc[mt2][nt2], aL[mt2], bH[nt2 >> 1][(nt2 & 1) * 2],
                                 bH[nt2 >> 1][(nt2 & 1) * 2 + 1]);
            }
            {
                uint32_t bL[2][4];
                #pragma unroll
                for (int nq = 0; nq < 2; nq++)
                    ldmat_x4(bL[nq], smb + SM_BLO + sw_unit(nb + nq * 16, ub) * 16);
                #pragma unroll
                for (int mt2 = 0; mt2 < 2; mt2++)
                    #pragma unroll
                    for (int nt2 = 0; nt2 < 4; nt2++)
                        mma_bf16(acc[mt2][nt2], aH[mt2], bL[nt2 >> 1][(nt2 & 1) * 2],
                                 bL[nt2 >> 1][(nt2 & 1) * 2 + 1]);
            }
        }
        __syncthreads();
    }

    // ---------------- epilogue ----------------
    const int qr = lane >> 2;
    const int qc = (lane & 3) * 2;
    #pragma unroll
    for (int mt2 = 0; mt2 < 2; mt2++) {
        #pragma unroll
        for (int nt2 = 0; nt2 < 4; nt2++) {
            int cl = wn0 + nt2 * 8 + qc;
            float* c = acc[mt2][nt2];
            #pragma unroll
            for (int rr = 0; rr < 2; rr++) {
                int e = m0 + wm0 + mt2 * 16 + qr + rr * 8;
                if (e >= E) continue;
                float v0 = c[rr * 2], v1 = c[rr * 2 + 1];
                if (mode_ep == 4) {
                    v0 *= S128; v1 *= S128;
                    if (plane == 0 && bias) { v0 += bias[cl]; v1 += bias[cl + 1]; }
                    int n = plane * 128 + cl;
                    OUT[(size_t)e * ldo + n]     = v0;
                    OUT[(size_t)e * ldo + n + 1] = v1;
                } else {
                    int n = ntb * 128 + cl;
                    if (bias) { v0 += bias[n]; v1 += bias[n + 1]; }
                    if (mode_ep == 1) { v0 = silu_f(v0); v1 = silu_f(v1); }
                    else if (mode_ep == 2) {
                        v0 *= mul[(size_t)e * MUL + cl];
                        v1 *= mul[(size_t)e * MUL + cl + 1];
                    }
                    OUT[(size_t)e * ldo + n]     = v0;
                    OUT[(size_t)e * ldo + n + 1] = v1;
                }
            }
        }
    }
}

// ---------------- launch ----------------
extern "C" void kernel_launch(void* const* d_in, const int* in_sizes, int n_in,
                              void* d_out, int out_size) {
    const float* node_attr = (const float*)d_in[0];
    const float* edge_attr = (const float*)d_in[1];
    const int*   dst       = (const int*)d_in[2];
    const int*   src       = (const int*)d_in[3];
    const float* npa       = (const float*)d_in[4];
    const float* W_inner   = (const float*)d_in[5];
    const float* b_inner   = (const float*)d_in[6];
    const float* W_n       = (const float*)d_in[7];
    const float* b_n       = (const float*)d_in[8];
    const float* W_out     = (const float*)d_in[9];
    const float* b_out     = (const float*)d_in[10];
    const float* pW1       = (const float*)d_in[11];
    const float* pb1       = (const float*)d_in[12];
    const float* pW2       = (const float*)d_in[13];
    const float* pb2       = (const float*)d_in[14];
    const float* gW1       = (const float*)d_in[15];
    const float* gb1       = (const float*)d_in[16];
    const float* gW2       = (const float*)d_in[17];
    const float* gb2       = (const float*)d_in[18];
    const float* fcEW1     = (const float*)d_in[19];
    const float* fcEW2     = (const float*)d_in[20];
    const float* fcW1      = (const float*)d_in[21];
    const float* fcb1      = (const float*)d_in[22];
    const float* fcW2      = (const float*)d_in[23];
    const float* fcb2      = (const float*)d_in[24];

    int N = in_sizes[0] / TOT;
    int E = in_sizes[2];
    int mt = (E + MT - 1) / MT;
    int nt = (N + MT - 1) / MT;

    void *p_h, *p_w, *p_np, *p_g, *p_pwhi, *p_pwlo, *p_we_;
    void *p_xp, *p_nf, *p_nh, *p_ng, *p_na0, *p_na;
    cudaGetSymbolAddress(&p_h,   g_h);
    cudaGetSymbolAddress(&p_w,   g_w);
    cudaGetSymbolAddress(&p_np,  g_np);
    cudaGetSymbolAddress(&p_g,   g_g);
    cudaGetSymbolAddress(&p_pwhi, g_pw_hi);
    cudaGetSymbolAddress(&p_pwlo, g_pw_lo);
    cudaGetSymbolAddress(&p_xp,  g_xp);
    cudaGetSymbolAddress(&p_nf,  g_nf);
    cudaGetSymbolAddress(&p_nh,  g_nh);
    cudaGetSymbolAddress(&p_ng,  g_ng);
    cudaGetSymbolAddress(&p_na0, g_na0);
    cudaGetSymbolAddress(&p_na,  g_na);
    cudaGetSymbolAddress(&p_we_, g_we);
    const __nv_bfloat16* pwhi = (const __nv_bfloat16*)p_pwhi;
    const __nv_bfloat16* pwlo = (const __nv_bfloat16*)p_pwlo;

    cudaFuncSetAttribute(gemm_kernel, cudaFuncAttributeMaxDynamicSharedMemorySize, SM_TOTAL);

    // L0: ALL weight prep in one launch
    prep_all<<<dim3((NM * NM + 255) / 256, 15), 256>>>(
        fcW1, fcW2, gW1, gW2, pW1, pW2, W_out, W_inner, W_n);

    k_xplan<<<(N * MUL + 255) / 256, 256>>>(node_attr, N);
    k_mtwe<<<(E + 1) / 2, 256>>>(edge_attr, fcEW1, fcEW2, E);

    // L3: na0 = irrep(xp, W_inner)
    gemm_kernel<<<dim3(nt, 9), GT, SM_TOTAL>>>(
        (const float*)p_xp, TOT, 2, pwhi + OFF_WIN, pwlo + OFF_WIN,
        (float*)p_na0, TOT, b_inner, nullptr, nullptr, nullptr, nullptr, 2, 4, N);

    // L4: nh = silu(nf @ pW1 + pb1)
    gemm_kernel<<<dim3(nt, 3), GT, SM_TOTAL>>>(
        (const float*)p_nf, NM, 6, pwhi + OFF_PW1, pwlo + OFF_PW1,
        (float*)p_nh, NM, pb1, nullptr, nullptr, nullptr, nullptr, 0, 1, N);

    // L5: ng = nh @ pW2 + pb2
    gemm_kernel<<<dim3(nt, 3), GT, SM_TOTAL>>>(
        (const float*)p_nh, NM, 6, pwhi + OFF_PW2, pwlo + OFF_PW2,
        (float*)p_ng, NM, pb2, nullptr, nullptr, nullptr, nullptr, 0, 0, N);

    k_gate_node<<<(N * MUL + 255) / 256, 256>>>(N);

    // L6: na = irrep(gated xp, W_n)
    gemm_kernel<<<dim3(nt, 9), GT, SM_TOTAL>>>(
        (const float*)p_xp, TOT, 2, pwhi + OFF_WN, pwlo + OFF_WN,
        (float*)p_na, TOT, b_n, nullptr, nullptr, nullptr, nullptr, 2, 4, N);

    // ---- edge stage ----
    // G1: h1 = silu(s0 @ fcW1 + fcb1), s0 computed in A-load from g_na0
    gemm_kernel<<<dim3(mt, 1), GT, SM_TOTAL>>>(
        (const float*)p_na0, TOT, 6, pwhi + OFF_FCW1, pwlo + OFF_FCW1,
        (float*)p_h, MUL, fcb1, nullptr, nullptr, dst, src, 3, 1, E);

    // G2: w = (h1 @ fcW2 + fcb2) * we
    gemm_kernel<<<dim3(mt, 1), GT, SM_TOTAL>>>(
        (const float*)p_h, MUL, 2, pwhi + OFF_FCW2, pwlo + OFF_FCW2,
        (float*)p_w, MUL, fcb2, (const float*)p_we_, nullptr, nullptr, nullptr, 0, 2, E);

    // G3: h = silu(f0' @ ngW1 + ngb1), f0' computed on the fly (mode 6)
    gemm_kernel<<<dim3(mt, 3), GT, SM_TOTAL>>>(
        (const float*)p_na, TOT, 6, pwhi + OFF_NGW1, pwlo + OFF_NGW1,
        (float*)p_h, NM, gb1, (const float*)p_w, nullptr, dst, src, 6, 1, E);

    // G4: g = h @ ngW2 + ngb2
    gemm_kernel<<<dim3(mt, 3), GT, SM_TOTAL>>>(
        (const float*)p_h, NM, 6, pwhi + OFF_NGW2, pwlo + OFF_NGW2,
        (float*)p_g, NM, gb2, nullptr, nullptr, nullptr, nullptr, 0, 0, E);

    // G5: planar out = irrep(gate(np, g), W_out)*S128 (+bias plane0); np recomputed
    gemm_kernel<<<dim3(mt, 9), GT, SM_TOTAL>>>(
        (const float*)p_na, TOT, 2, pwhi + OFF_WOUT, pwlo + OFF_WOUT,
        (float*)p_np, TOT, b_out, (const float*)p_w, (const float*)p_g, dst, src, 1, 4, E);

    // merge + npa
    k_out<<<(E * (TOT / 4) + 255) / 256, 256>>>(npa, (float*)d_out, E);
}

// round 15
// speedup vs baseline: 1.3100x; 1.3100x over previous
#include <cuda_runtime.h>
#include <cuda_bf16.h>
#include <cstdint>
#include <cstddef>

#define MUL 128
#define TOT 1152
#define NM  384
#define MAXN 4096
#define MAXE 65536
#define S128 0.08838834764831845f
#define IS3  0.57735026918962576f
#define IS5  0.44721359549995794f

// ---------------- scratch ----------------
__device__ float g_na0[MAXN * TOT];
__device__ float g_na [MAXN * TOT];
__device__ float g_xp [MAXN * TOT];
__device__ float g_nf [MAXN * NM];
__device__ float g_nh [MAXN * NM];
__device__ float g_ng [MAXN * NM];
__device__ float g_s0f[(size_t)MAXE * NM];   // f0'
__device__ float g_we [(size_t)MAXE * MUL];
__device__ float g_h  [(size_t)MAXE * NM];
__device__ float g_w  [(size_t)MAXE * MUL];
__device__ float g_np [(size_t)MAXE * TOT];
__device__ float g_g  [(size_t)MAXE * NM];

#define BLK 8192
#define OFF_FCW1 0
#define OFF_FCW2 49152
#define OFF_NGW1 65536
#define OFF_NGW2 212992
#define OFF_WOUT 360448
#define OFF_WIN  409600
#define OFF_WN   458752
#define OFF_PW1  507904
#define OFF_PW2  655360
#define PW_TOTAL 802816
__device__ __nv_bfloat16 g_pw_hi[PW_TOTAL];
__device__ __nv_bfloat16 g_pw_lo[PW_TOTAL];

__device__ __forceinline__ uint32_t smem_to_u32(const void* p) {
    uint32_t a;
    asm("{ .reg .u64 t; cvta.to.shared.u64 t, %1; cvt.u32.u64 %0, t; }" : "=r"(a) : "l"(p));
    return a;
}
__device__ __forceinline__ float silu_f(float x) { return x / (1.0f + __expf(-x)); }
__device__ __forceinline__ float ssp_f(float x) {
    return fmaxf(x, 0.0f) + log1pf(__expf(-fabsf(x))) - 0.69314718055994531f;
}
__device__ __forceinline__ int sw_unit(int row, int u) {
    return row * 8 + (u ^ (row & 7));
}
__device__ __forceinline__ int merged_to_planar(int j) {
    if (j < 128) return j;
    if (j < 512) { int r = j - 128; int u = r / 3; int c = r - 3 * u; return (1 + c) * 128 + u; }
    int r = j - 512; int u = r / 5; int c = r - 5 * u; return (4 + c) * 128 + u;
}

__device__ __forceinline__ void ldmat_x4(uint32_t* r, uint32_t addr) {
    asm volatile("ldmatrix.sync.aligned.m8n8.x4.shared.b16 {%0,%1,%2,%3}, [%4];"
        : "=r"(r[0]), "=r"(r[1]), "=r"(r[2]), "=r"(r[3]) : "r"(addr));
}
__device__ __forceinline__ void mma_bf16(float* c, const uint32_t* a, uint32_t b0, uint32_t b1) {
    asm volatile("mma.sync.aligned.m16n8k16.row.col.f32.bf16.bf16.f32 "
        "{%0,%1,%2,%3}, {%4,%5,%6,%7}, {%8,%9}, {%0,%1,%2,%3};"
        : "+f"(c[0]), "+f"(c[1]), "+f"(c[2]), "+f"(c[3])
        : "r"(a[0]), "r"(a[1]), "r"(a[2]), "r"(a[3]), "r"(b0), "r"(b1));
}
__device__ __forceinline__ void cp_async16(uint32_t dst, const void* src) {
    asm volatile("cp.async.cg.shared.global [%0], [%1], 16;" :: "r"(dst), "l"(src));
}
#define CP_COMMIT() asm volatile("cp.async.commit_group;" ::: "memory")
#define CP_WAIT0()  asm volatile("cp.async.wait_group 0;" ::: "memory")

// ---------------- batched weight prep ----------------
__global__ void prep_all(
    const float* __restrict__ fcW1, const float* __restrict__ fcW2,
    const float* __restrict__ gW1,  const float* __restrict__ gW2,
    const float* __restrict__ pW1,  const float* __restrict__ pW2,
    const float* __restrict__ Wout, const float* __restrict__ Win,
    const float* __restrict__ Wn)
{
    int job = blockIdx.y;
    const float* W;
    int K, Nn, off;
    switch (job) {
        case 0:  W = fcW1; K = NM;  Nn = MUL; off = OFF_FCW1; break;
        case 1:  W = fcW2; K = MUL; Nn = MUL; off = OFF_FCW2; break;
        case 2:  W = gW1;  K = NM;  Nn = NM;  off = OFF_NGW1; break;
        case 3:  W = gW2;  K = NM;  Nn = NM;  off = OFF_NGW2; break;
        case 4:  W = pW1;  K = NM;  Nn = NM;  off = OFF_PW1;  break;
        case 5:  W = pW2;  K = NM;  Nn = NM;  off = OFF_PW2;  break;
        default: {
            int grp = (job - 6) / 3;
            int i   = (job - 6) % 3;
            const float* base = (grp == 0) ? Wout : (grp == 1) ? Win : Wn;
            int boff = (grp == 0) ? OFF_WOUT : (grp == 1) ? OFF_WIN : OFF_WN;
            W = base + i * MUL * MUL; K = MUL; Nn = MUL; off = boff + i * 2 * BLK;
            break;
        }
    }
    int idx = blockIdx.x * blockDim.x + threadIdx.x;
    if (idx >= K * Nn) return;
    int kg = idx / Nn, ng = idx - kg * Nn;
    float x = W[idx];
    __nv_bfloat16 h = __float2bfloat16(x);
    __nv_bfloat16 l = __float2bfloat16(x - __bfloat162float(h));
    int kch = K >> 6;
    int nt = ng >> 7, n = ng & 127, kc = kg >> 6, k = kg & 63;
    int blk = nt * kch + kc;
    int e = blk * BLK + sw_unit(n, k >> 3) * 8 + (k & 7) + off;
    g_pw_hi[e] = h;
    g_pw_lo[e] = l;
}

// ---------------- elementwise kernels ----------------
__global__ void k_xplan(const float* __restrict__ na, int N) {
    int idx = blockIdx.x * blockDim.x + threadIdx.x;
    if (idx >= N * MUL) return;
    int n = idx >> 7, u = idx & 127;
    const float* x = na + (size_t)n * TOT;
    float v[9];
    v[0] = x[u];
    #pragma unroll
    for (int c = 0; c < 3; c++) v[1 + c] = x[128 + u * 3 + c];
    #pragma unroll
    for (int c = 0; c < 5; c++) v[4 + c] = x[512 + u * 5 + c];
    float* xp = g_xp + (size_t)n * TOT;
    #pragma unroll
    for (int p = 0; p < 9; p++) xp[p * 128 + u] = v[p];
    float* f = g_nf + (size_t)n * NM;
    f[u] = v[0];
    f[128 + u] = sqrtf(v[1] * v[1] + v[2] * v[2] + v[3] * v[3]);
    f[256 + u] = sqrtf(v[4] * v[4] + v[5] * v[5] + v[6] * v[6] + v[7] * v[7] + v[8] * v[8]);
}

__global__ void k_gate_node(int N) {
    int idx = blockIdx.x * blockDim.x + threadIdx.x;
    if (idx >= N * MUL) return;
    int n = idx >> 7, u = idx & 127;
    const float* g = g_ng + (size_t)n * NM;
    float* xp = g_xp + (size_t)n * TOT;
    float g1 = g[128 + u], g2 = g[256 + u];
    xp[u] = g[u];
    #pragma unroll
    for (int p = 1; p < 4; p++) xp[p * 128 + u] *= g1;
    #pragma unroll
    for (int p = 4; p < 9; p++) xp[p * 128 + u] *= g2;
}

__global__ void k_mtwe(const float* __restrict__ ea,
                       const float* __restrict__ W1, const float* __restrict__ W2, int E) {
    __shared__ float smt[2][8];
    int half = threadIdx.x >> 7;
    int t = threadIdx.x & 127;
    int e = blockIdx.x * 2 + half;
    int ec = (e < E) ? e : (E - 1);
    if (t < 8) {
        const float* a = ea + (size_t)ec * 64;
        float acc = 0.0f;
        #pragma unroll 16
        for (int i = 0; i < 64; i++) acc += a[i] * W1[i * 8 + t];
        smt[half][t] = ssp_f(acc * 0.125f);
    }
    __syncthreads();
    if (e < E) {
        float acc = 0.0f;
        #pragma unroll
        for (int j = 0; j < 8; j++) acc += smt[half][j] * W2[j * MUL + t];
        g_we[(size_t)e * MUL + t] = acc * 0.35355339059327373f;
    }
}

__global__ void k_f0(const int* __restrict__ dst, const int* __restrict__ src, int E) {
    int idx = blockIdx.x * blockDim.x + threadIdx.x;
    if (idx >= E * MUL) return;
    int e = idx >> 7, u = idx & 127;
    const float* ns = g_na + (size_t)src[e] * TOT;
    const float* nd = g_na + (size_t)dst[e] * TOT;
    const float* w = g_w + (size_t)e * MUL;
    float np[9];
    np[0] = (ns[u] + nd[u]) * w[u / 9];
    #pragma unroll
    for (int p = 1; p < 4; p++) {
        int j = 128 + u * 3 + (p - 1);
        np[p] = (ns[p * 128 + u] + nd[p * 128 + u]) * w[j / 9];
    }
    #pragma unroll
    for (int p = 4; p < 9; p++) {
        int j = 512 + u * 5 + (p - 4);
        np[p] = (ns[p * 128 + u] + nd[p * 128 + u]) * w[j / 9];
    }
    float* f = g_s0f + (size_t)e * NM;
    f[u] = np[0];
    f[128 + u] = sqrtf(np[1] * np[1] + np[2] * np[2] + np[3] * np[3]);
    f[256 + u] = sqrtf(np[4] * np[4] + np[5] * np[5] + np[6] * np[6]
                     + np[7] * np[7] + np[8] * np[8]);
}

__global__ void k_out(const float* __restrict__ npa, float* __restrict__ out, int E) {
    int idx = blockIdx.x * blockDim.x + threadIdx.x;
    if (idx >= E * (TOT / 4)) return;
    int e = idx / (TOT / 4);
    int j4 = (idx - e * (TOT / 4)) * 4;
    const float* pl = g_np + (size_t)e * TOT;
    float4 npv = *(const float4*)(npa + (size_t)e * TOT + j4);
    float4 o;
    o.x = pl[merged_to_planar(j4)]     + npv.x;
    o.y = pl[merged_to_planar(j4 + 1)] + npv.y;
    o.z = pl[merged_to_planar(j4 + 2)] + npv.z;
    o.w = pl[merged_to_planar(j4 + 3)] + npv.w;
    *(float4*)(out + (size_t)e * TOT + j4) = o;
}

// ---------------- mma.sync GEMM: 64x128 tile, 3 CTAs/SM ----------------
// 8 warps as 2m x 4n, warp tile 32x32, acc 32 regs/thread.
#define GT 256
#define MT 64
#define SM_AHI 0
#define SM_ALO 8192
#define SM_BHI 16384
#define SM_BLO 32768
#define SM_IDX 49152
#define SM_TOTAL 49664

// mode_a: 0 plain; 1 G5 np recompute (plane=by); 2 planar plain (plane=by); 3 G1 s0
// mode_ep: 0 +bias ; 1 silu(+bias) ; 2 (acc+bias)*mul ; 4 planar *S128 (+bias if plane0)
__global__ void __launch_bounds__(GT, 3) gemm_kernel(
    const float* __restrict__ A, int lda, int kchunks,
    const __nv_bfloat16* __restrict__ Bhi, const __nv_bfloat16* __restrict__ Blo,
    float* __restrict__ OUT, int ldo,
    const float* __restrict__ bias,
    const float* __restrict__ mul,
    const float* __restrict__ gate,
    const int* __restrict__ dstp, const int* __restrict__ srcp,
    int mode_a, int mode_ep, int E)
{
    extern __shared__ char smg[];
    uint32_t smb = smem_to_u32(smg);
    int* SIDX = (int*)(smg + SM_IDX);
    const int tid = threadIdx.x;
    const int wid = tid >> 5;
    const int lane = tid & 31;
    const int m0 = blockIdx.x * MT;
    const int by = blockIdx.y;
    const int plane = (mode_a == 1 || mode_a == 2) ? by : 0;
    const int ntb = (mode_a == 1 || mode_a == 2) ? 0 : by;

    const int wm0 = (wid & 1) * 32;       // 2 m-warps
    const int wn0 = (wid >> 1) * 32;      // 4 n-warps

    if (mode_a == 1 || mode_a == 3) {
        if (tid < MT) {
            int e = m0 + tid; if (e >= E) e = E - 1;
            SIDX[tid] = dstp[e];
            SIDX[MT + tid] = srcp[e];
        }
        __syncthreads();
    }

    float acc[2][4][4];
    #pragma unroll
    for (int i = 0; i < 2; i++)
        #pragma unroll
        for (int j = 0; j < 4; j++)
            #pragma unroll
            for (int q = 0; q < 4; q++) acc[i][j][q] = 0.0f;

    int bsel = ntb;
    if (mode_a == 1 || mode_a == 2) bsel = (plane == 0) ? 0 : (plane < 4 ? 1 : 2);

    for (int kc = 0; kc < kchunks; kc++) {
        // B tile via cp.async.cg (overlaps A convert below)
        {
            int blk = bsel * kchunks + kc;
            const char* sH = (const char*)(Bhi + (size_t)blk * BLK);
            const char* sL = (const char*)(Blo + (size_t)blk * BLK);
            #pragma unroll
            for (int it = 0; it < 4; it++) {
                int i = tid + it * GT;
                cp_async16(smb + SM_BHI + i * 16, sH + i * 16);
                cp_async16(smb + SM_BLO + i * 16, sL + i * 16);
            }
            CP_COMMIT();
        }
        // A tile: 64 rows x 64 k = 512 units, 2 per thread
        #pragma unroll
        for (int it = 0; it < 2; it++) {
            int i = tid + it * GT;
            int r = i >> 3, u = i & 7;
            int e = m0 + r;
            int k0 = u * 8;
            float v[8];
            #pragma unroll
            for (int q = 0; q < 8; q++) v[q] = 0.0f;
            if (e < E) {
                if (mode_a == 0) {
                    const float* p = A + (size_t)e * lda + kc * 64 + k0;
                    float4 v0 = *(const float4*)(p);
                    float4 v1 = *(const float4*)(p + 4);
                    v[0]=v0.x; v[1]=v0.y; v[2]=v0.z; v[3]=v0.w;
                    v[4]=v1.x; v[5]=v1.y; v[6]=v1.z; v[7]=v1.w;
                } else if (mode_a == 2) {
                    const float* p = A + (size_t)e * lda + plane * 128 + kc * 64 + k0;
                    float4 v0 = *(const float4*)(p);
                    float4 v1 = *(const float4*)(p + 4);
                    v[0]=v0.x; v[1]=v0.y; v[2]=v0.z; v[3]=v0.w;
                    v[4]=v1.x; v[5]=v1.y; v[6]=v1.z; v[7]=v1.w;
                } else if (mode_a == 1) {
                    if (plane == 0) {
                        const float* p = gate + (size_t)e * NM + kc * 64 + k0;
                        float4 v0 = *(const float4*)(p);
                        float4 v1 = *(const float4*)(p + 4);
                        v[0]=v0.x; v[1]=v0.y; v[2]=v0.z; v[3]=v0.w;
                        v[4]=v1.x; v[5]=v1.y; v[6]=v1.z; v[7]=v1.w;
                    } else {
                        const float* nd = A + (size_t)SIDX[r] * TOT + plane * 128 + kc * 64 + k0;
                        const float* ns = A + (size_t)SIDX[MT + r] * TOT + plane * 128 + kc * 64 + k0;
                        int go = (plane < 4) ? 128 : 256;
                        const float* gp = gate + (size_t)e * NM + go + kc * 64 + k0;
                        const float* wr = mul + (size_t)e * MUL;
                        #pragma unroll
                        for (int q = 0; q < 8; q++) {
                            int k = kc * 64 + k0 + q;
                            int j = (plane < 4) ? (128 + k * 3 + (plane - 1))
                                                : (512 + k * 5 + (plane - 4));
                            v[q] = (nd[q] + ns[q]) * wr[j / 9] * gp[q];
                        }
                    }
                } else { // mode_a == 3: s0 from g_na0 gathers
                    const float* nd = A + (size_t)SIDX[r] * TOT;
                    const float* ns = A + (size_t)SIDX[MT + r] * TOT;
                    int kg = kc * 64 + k0;
                    if (kg < 128) {
                        #pragma unroll
                        for (int q = 0; q < 8; q++)
                            v[q] = 0.5f * (nd[kg + q] + ns[kg + q]);
                    } else if (kg < 256) {
                        int u0 = kg - 128;
                        #pragma unroll
                        for (int q = 0; q < 8; q++) {
                            int uu = u0 + q;
                            v[q] = (nd[128 + uu] * ns[128 + uu] + nd[256 + uu] * ns[256 + uu]
                                  + nd[384 + uu] * ns[384 + uu]) * IS3;
                        }
                    } else {
                        int u0 = kg - 256;
                        #pragma unroll
                        for (int q = 0; q < 8; q++) {
                            int uu = u0 + q;
                            v[q] = (nd[512 + uu] * ns[512 + uu] + nd[640 + uu] * ns[640 + uu]
                                  + nd[768 + uu] * ns[768 + uu] + nd[896 + uu] * ns[896 + uu]
                                  + nd[1024 + uu] * ns[1024 + uu]) * IS5;
                        }
                    }
                }
            }
            uint32_t hi[4], lo[4];
            #pragma unroll
            for (int q = 0; q < 4; q++) {
                __nv_bfloat16 h0 = __float2bfloat16(v[2*q]);
                __nv_bfloat16 h1 = __float2bfloat16(v[2*q+1]);
                __nv_bfloat16 l0 = __float2bfloat16(v[2*q]   - __bfloat162float(h0));
                __nv_bfloat16 l1 = __float2bfloat16(v[2*q+1] - __bfloat162float(h1));
                __nv_bfloat162 h2(h0, h1), l2(l0, l1);
                hi[q] = *(uint32_t*)&h2;
                lo[q] = *(uint32_t*)&l2;
            }
            int off = sw_unit(r, u) * 16;
            *(uint4*)(smg + SM_AHI + off) = make_uint4(hi[0], hi[1], hi[2], hi[3]);
            *(uint4*)(smg + SM_ALO + off) = make_uint4(lo[0], lo[1], lo[2], lo[3]);
        }
        CP_WAIT0();
        __syncthreads();

        // MMA with cross-pass fragment reuse (8 ldmatrix.x4 per ks)
        #pragma unroll
        for (int ks = 0; ks < 4; ks++) {
            const int ua = ks * 2 + (lane >> 4);
            const int ub = ks * 2 + ((lane >> 3) & 1);
            const int rowa0 = wm0 + (lane & 15);
            const int nb = wn0 + (lane >> 4) * 8 + (lane & 7);

            uint32_t aH[2][4];
            #pragma unroll
            for (int mt2 = 0; mt2 < 2; mt2++)
                ldmat_x4(aH[mt2], smb + SM_AHI + sw_unit(rowa0 + mt2 * 16, ua) * 16);
            uint32_t bH[2][4];
            #pragma unroll
            for (int nq = 0; nq < 2; nq++)
                ldmat_x4(bH[nq], smb + SM_BHI + sw_unit(nb + nq * 16, ub) * 16);
            #pragma unroll
            for (int mt2 = 0; mt2 < 2; mt2++)
                #pragma unroll
                for (int nt2 = 0; nt2 < 4; nt2++)
                    mma_bf16(acc[mt2][nt2], aH[mt2], bH[nt2 >> 1][(nt2 & 1) * 2],
                             bH[nt2 >> 1][(nt2 & 1) * 2 + 1]);
            {
                uint32_t aL[2][4];
                #pragma unroll
                for (int mt2 = 0; mt2 < 2; mt2++)
                    ldmat_x4(aL[mt2], smb + SM_ALO + sw_unit(rowa0 + mt2 * 16, ua) * 16);
                #pragma unroll
                for (int mt2 = 0; mt2 < 2; mt2++)
                    #pragma unroll
                    for (int nt2 = 0; nt2 < 4; nt2++)
                        mma_bf16(acc[mt2][nt2], aL[mt2], bH[nt2 >> 1][(nt2 & 1) * 2],
                                 bH[nt2 >> 1][(nt2 & 1) * 2 + 1]);
            }
            {
                uint32_t bL[2][4];
                #pragma unroll
                for (int nq = 0; nq < 2; nq++)
                    ldmat_x4(bL[nq], smb + SM_BLO + sw_unit(nb + nq * 16, ub) * 16);
                #pragma unroll
                for (int mt2 = 0; mt2 < 2; mt2++)
                    #pragma unroll
                    for (int nt2 = 0; nt2 < 4; nt2++)
                        mma_bf16(acc[mt2][nt2], aH[mt2], bL[nt2 >> 1][(nt2 & 1) * 2],
                                 bL[nt2 >> 1][(nt2 & 1) * 2 + 1]);
            }
        }
        __syncthreads();
    }

    // ---------------- epilogue ----------------
    const int qr = lane >> 2;
    const int qc = (lane & 3) * 2;
    #pragma unroll
    for (int mt2 = 0; mt2 < 2; mt2++) {
        #pragma unroll
        for (int nt2 = 0; nt2 < 4; nt2++) {
            int cl = wn0 + nt2 * 8 + qc;
            float* c = acc[mt2][nt2];
            #pragma unroll
            for (int rr = 0; rr < 2; rr++) {
                int e = m0 + wm0 + mt2 * 16 + qr + rr * 8;
                if (e >= E) continue;
                float v0 = c[rr * 2], v1 = c[rr * 2 + 1];
                if (mode_ep == 4) {
                    v0 *= S128; v1 *= S128;
                    if (plane == 0 && bias) { v0 += bias[cl]; v1 += bias[cl + 1]; }
                    int n = plane * 128 + cl;
                    OUT[(size_t)e * ldo + n]     = v0;
                    OUT[(size_t)e * ldo + n + 1] = v1;
                } else {
                    int n = ntb * 128 + cl;
                    if (bias) { v0 += bias[n]; v1 += bias[n + 1]; }
                    if (mode_ep == 1) { v0 = silu_f(v0); v1 = silu_f(v1); }
                    else if (mode_ep == 2) {
                        v0 *= mul[(size_t)e * MUL + cl];
                        v1 *= mul[(size_t)e * MUL + cl + 1];
                    }
                    OUT[(size_t)e * ldo + n]     = v0;
                    OUT[(size_t)e * ldo + n + 1] = v1;
                }
            }
        }
    }
}

// ---------------- launch ----------------
extern "C" void kernel_launch(void* const* d_in, const int* in_sizes, int n_in,
                              void* d_out, int out_size) {
    const float* node_attr = (const float*)d_in[0];
    const float* edge_attr = (const float*)d_in[1];
    const int*   dst       = (const int*)d_in[2];
    const int*   src       = (const int*)d_in[3];
    const float* npa       = (const float*)d_in[4];
    const float* W_inner   = (const float*)d_in[5];
    const float* b_inner   = (const float*)d_in[6];
    const float* W_n       = (const float*)d_in[7];
    const float* b_n       = (const float*)d_in[8];
    const float* W_out     = (const float*)d_in[9];
    const float* b_out     = (const float*)d_in[10];
    const float* pW1       = (const float*)d_in[11];
    const float* pb1       = (const float*)d_in[12];
    const float* pW2       = (const float*)d_in[13];
    const float* pb2       = (const float*)d_in[14];
    const float* gW1       = (const float*)d_in[15];
    const float* gb1       = (const float*)d_in[16];
    const float* gW2       = (const float*)d_in[17];
    const float* gb2       = (const float*)d_in[18];
    const float* fcEW1     = (const float*)d_in[19];
    const float* fcEW2     = (const float*)d_in[20];
    const float* fcW1      = (const float*)d_in[21];
    const float* fcb1      = (const float*)d_in[22];
    const float* fcW2      = (const float*)d_in[23];
    const float* fcb2      = (const float*)d_in[24];

    int N = in_sizes[0] / TOT;
    int E = in_sizes[2];
    int mt = (E + MT - 1) / MT;
    int nt = (N + MT - 1) / MT;

    void *p_s0f, *p_h, *p_w, *p_np, *p_g, *p_pwhi, *p_pwlo, *p_we_;
    void *p_xp, *p_nf, *p_nh, *p_ng, *p_na0, *p_na;
    cudaGetSymbolAddress(&p_s0f, g_s0f);
    cudaGetSymbolAddress(&p_h,   g_h);
    cudaGetSymbolAddress(&p_w,   g_w);
    cudaGetSymbolAddress(&p_np,  g_np);
    cudaGetSymbolAddress(&p_g,   g_g);
    cudaGetSymbolAddress(&p_pwhi, g_pw_hi);
    cudaGetSymbolAddress(&p_pwlo, g_pw_lo);
    cudaGetSymbolAddress(&p_xp,  g_xp);
    cudaGetSymbolAddress(&p_nf,  g_nf);
    cudaGetSymbolAddress(&p_nh,  g_nh);
    cudaGetSymbolAddress(&p_ng,  g_ng);
    cudaGetSymbolAddress(&p_na0, g_na0);
    cudaGetSymbolAddress(&p_na,  g_na);
    cudaGetSymbolAddress(&p_we_, g_we);
    const __nv_bfloat16* pwhi = (const __nv_bfloat16*)p_pwhi;
    const __nv_bfloat16* pwlo = (const __nv_bfloat16*)p_pwlo;

    cudaFuncSetAttribute(gemm_kernel, cudaFuncAttributeMaxDynamicSharedMemorySize, SM_TOTAL);

    // L0: ALL weight prep in one launch
    prep_all<<<dim3((NM * NM + 255) / 256, 15), 256>>>(
        fcW1, fcW2, gW1, gW2, pW1, pW2, W_out, W_inner, W_n);

    k_xplan<<<(N * MUL + 255) / 256, 256>>>(node_attr, N);
    k_mtwe<<<(E + 1) / 2, 256>>>(edge_attr, fcEW1, fcEW2, E);

    // L3: na0 = irrep(xp, W_inner)
    gemm_kernel<<<dim3(nt, 9), GT, SM_TOTAL>>>(
        (const float*)p_xp, TOT, 2, pwhi + OFF_WIN, pwlo + OFF_WIN,
        (float*)p_na0, TOT, b_inner, nullptr, nullptr, nullptr, nullptr, 2, 4, N);

    // L4: nh = silu(nf @ pW1 + pb1)
    gemm_kernel<<<dim3(nt, 3), GT, SM_TOTAL>>>(
        (const float*)p_nf, NM, 6, pwhi + OFF_PW1, pwlo + OFF_PW1,
        (float*)p_nh, NM, pb1, nullptr, nullptr, nullptr, nullptr, 0, 1, N);

    // L5: ng = nh @ pW2 + pb2
    gemm_kernel<<<dim3(nt, 3), GT, SM_TOTAL>>>(
        (const float*)p_nh, NM, 6, pwhi + OFF_PW2, pwlo + OFF_PW2,
        (float*)p_ng, NM, pb2, nullptr, nullptr, nullptr, nullptr, 0, 0, N);

    k_gate_node<<<(N * MUL + 255) / 256, 256>>>(N);

    // L6: na = irrep(gated xp, W_n)
    gemm_kernel<<<dim3(nt, 9), GT, SM_TOTAL>>>(
        (const float*)p_xp, TOT, 2, pwhi + OFF_WN, pwlo + OFF_WN,
        (float*)p_na, TOT, b_n, nullptr, nullptr, nullptr, nullptr, 2, 4, N);

    // ---- edge stage ----
    // G1: h1 = silu(s0 @ fcW1 + fcb1), s0 computed in A-load from g_na0
    gemm_kernel<<<dim3(mt, 1), GT, SM_TOTAL>>>(
        (const float*)p_na0, TOT, 6, pwhi + OFF_FCW1, pwlo + OFF_FCW1,
        (float*)p_h, MUL, fcb1, nullptr, nullptr, dst, src, 3, 1, E);

    // G2: w = (h1 @ fcW2 + fcb2) * we
    gemm_kernel<<<dim3(mt, 1), GT, SM_TOTAL>>>(
        (const float*)p_h, MUL, 2, pwhi + OFF_FCW2, pwlo + OFF_FCW2,
        (float*)p_w, MUL, fcb2, (const float*)p_we_, nullptr, nullptr, nullptr, 0, 2, E);

    // f0'
    k_f0<<<(E * MUL + 255) / 256, 256>>>(dst, src, E);

    // G3: h = silu(f0' @ ngW1 + ngb1)
    gemm_kernel<<<dim3(mt, 3), GT, SM_TOTAL>>>(
        (const float*)p_s0f, NM, 6, pwhi + OFF_NGW1, pwlo + OFF_NGW1,
        (float*)p_h, NM, gb1, nullptr, nullptr, nullptr, nullptr, 0, 1, E);

    // G4: g = h @ ngW2 + ngb2
    gemm_kernel<<<dim3(mt, 3), GT, SM_TOTAL>>>(
        (const float*)p_h, NM, 6, pwhi + OFF_NGW2, pwlo + OFF_NGW2,
        (float*)p_g, NM, gb2, nullptr, nullptr, nullptr, nullptr, 0, 0, E);

    // G5: planar out = irrep(gate(np, g), W_out)*S128 (+bias plane0); np recomputed
    gemm_kernel<<<dim3(mt, 9), GT, SM_TOTAL>>>(
        (const float*)p_na, TOT, 2, pwhi + OFF_WOUT, pwlo + OFF_WOUT,
        (float*)p_np, TOT, b_out, (const float*)p_w, (const float*)p_g, dst, src, 1, 4, E);

    // merge + npa
    k_out<<<(E * (TOT / 4) + 255) / 256, 256>>>(npa, (float*)d_out, E);
}

// round 16
// speedup vs baseline: 1.3886x; 1.0600x over previous
#include <cuda_runtime.h>
#include <cuda_bf16.h>
#include <cstdint>
#include <cstddef>

#define MUL 128
#define TOT 1152
#define NM  384
#define MAXN 4096
#define MAXE 65536
#define S128 0.08838834764831845f
#define IS3  0.57735026918962576f
#define IS5  0.44721359549995794f

// ---------------- scratch ----------------
__device__ float g_na0[MAXN * TOT];
__device__ float g_na [MAXN * TOT];
__device__ float g_xp [MAXN * TOT];
__device__ float g_nf [MAXN * NM];
__device__ float g_nh [MAXN * NM];
__device__ float g_ng [MAXN * NM];
__device__ float g_s0f[(size_t)MAXE * NM];   // f0'
__device__ float g_we [(size_t)MAXE * MUL];
__device__ float g_h  [(size_t)MAXE * NM];
__device__ float g_w  [(size_t)MAXE * MUL];
__device__ float g_np [(size_t)MAXE * TOT];
__device__ float g_g  [(size_t)MAXE * NM];

#define BLK 8192
#define OFF_FCW1 0
#define OFF_FCW2 49152
#define OFF_NGW1 65536
#define OFF_NGW2 212992
#define OFF_WOUT 360448
#define OFF_WIN  409600
#define OFF_WN   458752
#define OFF_PW1  507904
#define OFF_PW2  655360
#define PW_TOTAL 802816
__device__ __nv_bfloat16 g_pw_hi[PW_TOTAL];
__device__ __nv_bfloat16 g_pw_lo[PW_TOTAL];

__device__ __forceinline__ uint32_t smem_to_u32(const void* p) {
    uint32_t a;
    asm("{ .reg .u64 t; cvta.to.shared.u64 t, %1; cvt.u32.u64 %0, t; }" : "=r"(a) : "l"(p));
    return a;
}
__device__ __forceinline__ float silu_f(float x) { return x / (1.0f + __expf(-x)); }
__device__ __forceinline__ float ssp_f(float x) {
    return fmaxf(x, 0.0f) + log1pf(__expf(-fabsf(x))) - 0.69314718055994531f;
}
__device__ __forceinline__ int sw_unit(int row, int u) {
    return row * 8 + (u ^ (row & 7));
}
__device__ __forceinline__ int merged_to_planar(int j) {
    if (j < 128) return j;
    if (j < 512) { int r = j - 128; int u = r / 3; int c = r - 3 * u; return (1 + c) * 128 + u; }
    int r = j - 512; int u = r / 5; int c = r - 5 * u; return (4 + c) * 128 + u;
}

__device__ __forceinline__ void ldmat_x4(uint32_t* r, uint32_t addr) {
    asm volatile("ldmatrix.sync.aligned.m8n8.x4.shared.b16 {%0,%1,%2,%3}, [%4];"
        : "=r"(r[0]), "=r"(r[1]), "=r"(r[2]), "=r"(r[3]) : "r"(addr));
}
__device__ __forceinline__ void mma_bf16(float* c, const uint32_t* a, uint32_t b0, uint32_t b1) {
    asm volatile("mma.sync.aligned.m16n8k16.row.col.f32.bf16.bf16.f32 "
        "{%0,%1,%2,%3}, {%4,%5,%6,%7}, {%8,%9}, {%0,%1,%2,%3};"
        : "+f"(c[0]), "+f"(c[1]), "+f"(c[2]), "+f"(c[3])
        : "r"(a[0]), "r"(a[1]), "r"(a[2]), "r"(a[3]), "r"(b0), "r"(b1));
}
__device__ __forceinline__ void cp_async16(uint32_t dst, const void* src) {
    asm volatile("cp.async.cg.shared.global [%0], [%1], 16;" :: "r"(dst), "l"(src));
}
#define CP_COMMIT() asm volatile("cp.async.commit_group;" ::: "memory")
#define CP_WAIT0()  asm volatile("cp.async.wait_group 0;" ::: "memory")

// ---------------- batched weight prep ----------------
__global__ void prep_all(
    const float* __restrict__ fcW1, const float* __restrict__ fcW2,
    const float* __restrict__ gW1,  const float* __restrict__ gW2,
    const float* __restrict__ pW1,  const float* __restrict__ pW2,
    const float* __restrict__ Wout, const float* __restrict__ Win,
    const float* __restrict__ Wn)
{
    int job = blockIdx.y;
    const float* W;
    int K, Nn, off;
    switch (job) {
        case 0:  W = fcW1; K = NM;  Nn = MUL; off = OFF_FCW1; break;
        case 1:  W = fcW2; K = MUL; Nn = MUL; off = OFF_FCW2; break;
        case 2:  W = gW1;  K = NM;  Nn = NM;  off = OFF_NGW1; break;
        case 3:  W = gW2;  K = NM;  Nn = NM;  off = OFF_NGW2; break;
        case 4:  W = pW1;  K = NM;  Nn = NM;  off = OFF_PW1;  break;
        case 5:  W = pW2;  K = NM;  Nn = NM;  off = OFF_PW2;  break;
        default: {
            int grp = (job - 6) / 3;
            int i   = (job - 6) % 3;
            const float* base = (grp == 0) ? Wout : (grp == 1) ? Win : Wn;
            int boff = (grp == 0) ? OFF_WOUT : (grp == 1) ? OFF_WIN : OFF_WN;
            W = base + i * MUL * MUL; K = MUL; Nn = MUL; off = boff + i * 2 * BLK;
            break;
        }
    }
    int idx = blockIdx.x * blockDim.x + threadIdx.x;
    if (idx >= K * Nn) return;
    int kg = idx / Nn, ng = idx - kg * Nn;
    float x = W[idx];
    __nv_bfloat16 h = __float2bfloat16(x);
    __nv_bfloat16 l = __float2bfloat16(x - __bfloat162float(h));
    int kch = K >> 6;
    int nt = ng >> 7, n = ng & 127, kc = kg >> 6, k = kg & 63;
    int blk = nt * kch + kc;
    int e = blk * BLK + sw_unit(n, k >> 3) * 8 + (k & 7) + off;
    g_pw_hi[e] = h;
    g_pw_lo[e] = l;
}

// ---------------- elementwise kernels ----------------
__global__ void k_xplan(const float* __restrict__ na, int N) {
    int idx = blockIdx.x * blockDim.x + threadIdx.x;
    if (idx >= N * MUL) return;
    int n = idx >> 7, u = idx & 127;
    const float* x = na + (size_t)n * TOT;
    float v[9];
    v[0] = x[u];
    #pragma unroll
    for (int c = 0; c < 3; c++) v[1 + c] = x[128 + u * 3 + c];
    #pragma unroll
    for (int c = 0; c < 5; c++) v[4 + c] = x[512 + u * 5 + c];
    float* xp = g_xp + (size_t)n * TOT;
    #pragma unroll
    for (int p = 0; p < 9; p++) xp[p * 128 + u] = v[p];
    float* f = g_nf + (size_t)n * NM;
    f[u] = v[0];
    f[128 + u] = sqrtf(v[1] * v[1] + v[2] * v[2] + v[3] * v[3]);
    f[256 + u] = sqrtf(v[4] * v[4] + v[5] * v[5] + v[6] * v[6] + v[7] * v[7] + v[8] * v[8]);
}

__global__ void k_gate_node(int N) {
    int idx = blockIdx.x * blockDim.x + threadIdx.x;
    if (idx >= N * MUL) return;
    int n = idx >> 7, u = idx & 127;
    const float* g = g_ng + (size_t)n * NM;
    float* xp = g_xp + (size_t)n * TOT;
    float g1 = g[128 + u], g2 = g[256 + u];
    xp[u] = g[u];
    #pragma unroll
    for (int p = 1; p < 4; p++) xp[p * 128 + u] *= g1;
    #pragma unroll
    for (int p = 4; p < 9; p++) xp[p * 128 + u] *= g2;
}

__global__ void k_mtwe(const float* __restrict__ ea,
                       const float* __restrict__ W1, const float* __restrict__ W2, int E) {
    __shared__ float smt[2][8];
    int half = threadIdx.x >> 7;
    int t = threadIdx.x & 127;
    int e = blockIdx.x * 2 + half;
    int ec = (e < E) ? e : (E - 1);
    if (t < 8) {
        const float* a = ea + (size_t)ec * 64;
        float acc = 0.0f;
        #pragma unroll 16
        for (int i = 0; i < 64; i++) acc += a[i] * W1[i * 8 + t];
        smt[half][t] = ssp_f(acc * 0.125f);
    }
    __syncthreads();
    if (e < E) {
        float acc = 0.0f;
        #pragma unroll
        for (int j = 0; j < 8; j++) acc += smt[half][j] * W2[j * MUL + t];
        g_we[(size_t)e * MUL + t] = acc * 0.35355339059327373f;
    }
}

__global__ void k_f0(const int* __restrict__ dst, const int* __restrict__ src, int E) {
    int idx = blockIdx.x * blockDim.x + threadIdx.x;
    if (idx >= E * MUL) return;
    int e = idx >> 7, u = idx & 127;
    const float* ns = g_na + (size_t)src[e] * TOT;
    const float* nd = g_na + (size_t)dst[e] * TOT;
    const float* w = g_w + (size_t)e * MUL;
    float np[9];
    np[0] = (ns[u] + nd[u]) * w[u / 9];
    #pragma unroll
    for (int p = 1; p < 4; p++) {
        int j = 128 + u * 3 + (p - 1);
        np[p] = (ns[p * 128 + u] + nd[p * 128 + u]) * w[j / 9];
    }
    #pragma unroll
    for (int p = 4; p < 9; p++) {
        int j = 512 + u * 5 + (p - 4);
        np[p] = (ns[p * 128 + u] + nd[p * 128 + u]) * w[j / 9];
    }
    float* f = g_s0f + (size_t)e * NM;
    f[u] = np[0];
    f[128 + u] = sqrtf(np[1] * np[1] + np[2] * np[2] + np[3] * np[3]);
    f[256 + u] = sqrtf(np[4] * np[4] + np[5] * np[5] + np[6] * np[6]
                     + np[7] * np[7] + np[8] * np[8]);
}

__global__ void k_out(const float* __restrict__ npa, float* __restrict__ out, int E) {
    int idx = blockIdx.x * blockDim.x + threadIdx.x;
    if (idx >= E * (TOT / 4)) return;
    int e = idx / (TOT / 4);
    int j4 = (idx - e * (TOT / 4)) * 4;
    const float* pl = g_np + (size_t)e * TOT;
    float4 npv = *(const float4*)(npa + (size_t)e * TOT + j4);
    float4 o;
    o.x = pl[merged_to_planar(j4)]     + npv.x;
    o.y = pl[merged_to_planar(j4 + 1)] + npv.y;
    o.z = pl[merged_to_planar(j4 + 2)] + npv.z;
    o.w = pl[merged_to_planar(j4 + 3)] + npv.w;
    *(float4*)(out + (size_t)e * TOT + j4) = o;
}

// ---------------- mma.sync GEMM: 64x128 tile, 3 CTAs/SM ----------------
// 8 warps as 2m x 4n, warp tile 32x32, acc 32 regs/thread.
#define GT 256
#define MT 64
#define SM_AHI 0
#define SM_ALO 8192
#define SM_BHI 16384
#define SM_BLO 32768
#define SM_IDX 49152
#define SM_TOTAL 49664

// mode_a: 0 plain; 1 G5 np recompute (plane=by); 2 planar plain (plane=by); 3 G1 s0
// mode_ep: 0 +bias ; 1 silu(+bias) ; 2 (acc+bias)*mul ; 4 planar *S128 (+bias if plane0)
__global__ void __launch_bounds__(GT, 3) gemm_kernel(
    const float* __restrict__ A, int lda, int kchunks,
    const __nv_bfloat16* __restrict__ Bhi, const __nv_bfloat16* __restrict__ Blo,
    float* __restrict__ OUT, int ldo,
    const float* __restrict__ bias,
    const float* __restrict__ mul,
    const float* __restrict__ gate,
    const int* __restrict__ dstp, const int* __restrict__ srcp,
    int mode_a, int mode_ep, int E)
{
    extern __shared__ char smg[];
    uint32_t smb = smem_to_u32(smg);
    int* SIDX = (int*)(smg + SM_IDX);
    const int tid = threadIdx.x;
    const int wid = tid >> 5;
    const int lane = tid & 31;
    const int m0 = blockIdx.x * MT;
    const int by = blockIdx.y;
    const int plane = (mode_a == 1 || mode_a == 2) ? by : 0;
    const int ntb = (mode_a == 1 || mode_a == 2) ? 0 : by;

    const int wm0 = (wid & 1) * 32;       // 2 m-warps
    const int wn0 = (wid >> 1) * 32;      // 4 n-warps

    if (mode_a == 1 || mode_a == 3) {
        if (tid < MT) {
            int e = m0 + tid; if (e >= E) e = E - 1;
            SIDX[tid] = dstp[e];
            SIDX[MT + tid] = srcp[e];
        }
        __syncthreads();
    }

    float acc[2][4][4];
    #pragma unroll
    for (int i = 0; i < 2; i++)
        #pragma unroll
        for (int j = 0; j < 4; j++)
            #pragma unroll
            for (int q = 0; q < 4; q++) acc[i][j][q] = 0.0f;

    int bsel = ntb;
    if (mode_a == 1 || mode_a == 2) bsel = (plane == 0) ? 0 : (plane < 4 ? 1 : 2);

    for (int kc = 0; kc < kchunks; kc++) {
        // B tile via cp.async.cg (overlaps A convert below)
        {
            int blk = bsel * kchunks + kc;
            const char* sH = (const char*)(Bhi + (size_t)blk * BLK);
            const char* sL = (const char*)(Blo + (size_t)blk * BLK);
            #pragma unroll
            for (int it = 0; it < 4; it++) {
                int i = tid + it * GT;
                cp_async16(smb + SM_BHI + i * 16, sH + i * 16);
                cp_async16(smb + SM_BLO + i * 16, sL + i * 16);
            }
            CP_COMMIT();
        }
        // A tile: 64 rows x 64 k = 512 units, 2 per thread
        #pragma unroll
        for (int it = 0; it < 2; it++) {
            int i = tid + it * GT;
            int r = i >> 3, u = i & 7;
            int e = m0 + r;
            int k0 = u * 8;
            float v[8];
            #pragma unroll
            for (int q = 0; q < 8; q++) v[q] = 0.0f;
            if (e < E) {
                if (mode_a == 0) {
                    const float* p = A + (size_t)e * lda + kc * 64 + k0;
                    float4 v0 = *(const float4*)(p);
                    float4 v1 = *(const float4*)(p + 4);
                    v[0]=v0.x; v[1]=v0.y; v[2]=v0.z; v[3]=v0.w;
                    v[4]=v1.x; v[5]=v1.y; v[6]=v1.z; v[7]=v1.w;
                } else if (mode_a == 2) {
                    const float* p = A + (size_t)e * lda + plane * 128 + kc * 64 + k0;
                    float4 v0 = *(const float4*)(p);
                    float4 v1 = *(const float4*)(p + 4);
                    v[0]=v0.x; v[1]=v0.y; v[2]=v0.z; v[3]=v0.w;
                    v[4]=v1.x; v[5]=v1.y; v[6]=v1.z; v[7]=v1.w;
                } else if (mode_a == 1) {
                    if (plane == 0) {
                        const float* p = gate + (size_t)e * NM + kc * 64 + k0;
                        float4 v0 = *(const float4*)(p);
                        float4 v1 = *(const float4*)(p + 4);
                        v[0]=v0.x; v[1]=v0.y; v[2]=v0.z; v[3]=v0.w;
                        v[4]=v1.x; v[5]=v1.y; v[6]=v1.z; v[7]=v1.w;
                    } else {
                        const float* nd = A + (size_t)SIDX[r] * TOT + plane * 128 + kc * 64 + k0;
                        const float* ns = A + (size_t)SIDX[MT + r] * TOT + plane * 128 + kc * 64 + k0;
                        int go = (plane < 4) ? 128 : 256;
                        const float* gp = gate + (size_t)e * NM + go + kc * 64 + k0;
                        const float* wr = mul + (size_t)e * MUL;
                        #pragma unroll
                        for (int q = 0; q < 8; q++) {
                            int k = kc * 64 + k0 + q;
                            int j = (plane < 4) ? (128 + k * 3 + (plane - 1))
                                                : (512 + k * 5 + (plane - 4));
                            v[q] = (nd[q] + ns[q]) * wr[j / 9] * gp[q];
                        }
                    }
                } else { // mode_a == 3: s0 from g_na0 gathers
                    const float* nd = A + (size_t)SIDX[r] * TOT;
                    const float* ns = A + (size_t)SIDX[MT + r] * TOT;
                    int kg = kc * 64 + k0;
                    if (kg < 128) {
                        #pragma unroll
                        for (int q = 0; q < 8; q++)
                            v[q] = 0.5f * (nd[kg + q] + ns[kg + q]);
                    } else if (kg < 256) {
                        int u0 = kg - 128;
                        #pragma unroll
                        for (int q = 0; q < 8; q++) {
                            int uu = u0 + q;
                            v[q] = (nd[128 + uu] * ns[128 + uu] + nd[256 + uu] * ns[256 + uu]
                                  + nd[384 + uu] * ns[384 + uu]) * IS3;
                        }
                    } else {
                        int u0 = kg - 256;
                        #pragma unroll
                        for (int q = 0; q < 8; q++) {
                            int uu = u0 + q;
                            v[q] = (nd[512 + uu] * ns[512 + uu] + nd[640 + uu] * ns[640 + uu]
                                  + nd[768 + uu] * ns[768 + uu] + nd[896 + uu] * ns[896 + uu]
                                  + nd[1024 + uu] * ns[1024 + uu]) * IS5;
                        }
                    }
                }
            }
            uint32_t hi[4], lo[4];
            #pragma unroll
            for (int q = 0; q < 4; q++) {
                __nv_bfloat16 h0 = __float2bfloat16(v[2*q]);
                __nv_bfloat16 h1 = __float2bfloat16(v[2*q+1]);
                __nv_bfloat16 l0 = __float2bfloat16(v[2*q]   - __bfloat162float(h0));
                __nv_bfloat16 l1 = __float2bfloat16(v[2*q+1] - __bfloat162float(h1));
                __nv_bfloat162 h2(h0, h1), l2(l0, l1);
                hi[q] = *(uint32_t*)&h2;
                lo[q] = *(uint32_t*)&l2;
            }
            int off = sw_unit(r, u) * 16;
            *(uint4*)(smg + SM_AHI + off) = make_uint4(hi[0], hi[1], hi[2], hi[3]);
            *(uint4*)(smg + SM_ALO + off) = make_uint4(lo[0], lo[1], lo[2], lo[3]);
        }
        CP_WAIT0();
        __syncthreads();

        // MMA with cross-pass fragment reuse (8 ldmatrix.x4 per ks)
        #pragma unroll
        for (int ks = 0; ks < 4; ks++) {
            const int ua = ks * 2 + (lane >> 4);
            const int ub = ks * 2 + ((lane >> 3) & 1);
            const int rowa0 = wm0 + (lane & 15);
            const int nb = wn0 + (lane >> 4) * 8 + (lane & 7);

            uint32_t aH[2][4];
            #pragma unroll
            for (int mt2 = 0; mt2 < 2; mt2++)
                ldmat_x4(aH[mt2], smb + SM_AHI + sw_unit(rowa0 + mt2 * 16, ua) * 16);
            uint32_t bH[2][4];
            #pragma unroll
            for (int nq = 0; nq < 2; nq++)
                ldmat_x4(bH[nq], smb + SM_BHI + sw_unit(nb + nq * 16, ub) * 16);
            #pragma unroll
            for (int mt2 = 0; mt2 < 2; mt2++)
                #pragma unroll
                for (int nt2 = 0; nt2 < 4; nt2++)
                    mma_bf16(acc[mt2][nt2], aH[mt2], bH[nt2 >> 1][(nt2 & 1) * 2],
                             bH[nt2 >> 1][(nt2 & 1) * 2 + 1]);
            {
                uint32_t aL[2][4];
                #pragma unroll
                for (int mt2 = 0; mt2 < 2; mt2++)
                    ldmat_x4(aL[mt2], smb + SM_ALO + sw_unit(rowa0 + mt2 * 16, ua) * 16);
                #pragma unroll
                for (int mt2 = 0; mt2 < 2; mt2++)
                    #pragma unroll
                    for (int nt2 = 0; nt2 < 4; nt2++)
                        mma_bf16(acc[mt2][nt2], aL[mt2], bH[nt2 >> 1][(nt2 & 1) * 2],
                                 bH[nt2 >> 1][(nt2 & 1) * 2 + 1]);
            }
            {
                uint32_t bL[2][4];
                #pragma unroll
                for (int nq = 0; nq < 2; nq++)
                    ldmat_x4(bL[nq], smb + SM_BLO + sw_unit(nb + nq * 16, ub) * 16);
                #pragma unroll
                for (int mt2 = 0; mt2 < 2; mt2++)
                    #pragma unroll
                    for (int nt2 = 0; nt2 < 4; nt2++)
                        mma_bf16(acc[mt2][nt2], aH[mt2], bL[nt2 >> 1][(nt2 & 1) * 2],
                                 bL[nt2 >> 1][(nt2 & 1) * 2 + 1]);
            }
        }
        __syncthreads();
    }

    // ---------------- epilogue (paired float2 stores; n always even, 8B aligned) ----
    const int qr = lane >> 2;
    const int qc = (lane & 3) * 2;
    #pragma unroll
    for (int mt2 = 0; mt2 < 2; mt2++) {
        #pragma unroll
        for (int nt2 = 0; nt2 < 4; nt2++) {
            int cl = wn0 + nt2 * 8 + qc;
            float* c = acc[mt2][nt2];
            #pragma unroll
            for (int rr = 0; rr < 2; rr++) {
                int e = m0 + wm0 + mt2 * 16 + qr + rr * 8;
                if (e >= E) continue;
                float v0 = c[rr * 2], v1 = c[rr * 2 + 1];
                if (mode_ep == 4) {
                    v0 *= S128; v1 *= S128;
                    if (plane == 0 && bias) { v0 += bias[cl]; v1 += bias[cl + 1]; }
                    int n = plane * 128 + cl;
                    *(float2*)(OUT + (size_t)e * ldo + n) = make_float2(v0, v1);
                } else {
                    int n = ntb * 128 + cl;
                    if (bias) { v0 += bias[n]; v1 += bias[n + 1]; }
                    if (mode_ep == 1) { v0 = silu_f(v0); v1 = silu_f(v1); }
                    else if (mode_ep == 2) {
                        v0 *= mul[(size_t)e * MUL + cl];
                        v1 *= mul[(size_t)e * MUL + cl + 1];
                    }
                    *(float2*)(OUT + (size_t)e * ldo + n) = make_float2(v0, v1);
                }
            }
        }
    }
}

// ---------------- launch ----------------
extern "C" void kernel_launch(void* const* d_in, const int* in_sizes, int n_in,
                              void* d_out, int out_size) {
    const float* node_attr = (const float*)d_in[0];
    const float* edge_attr = (const float*)d_in[1];
    const int*   dst       = (const int*)d_in[2];
    const int*   src       = (const int*)d_in[3];
    const float* npa       = (const float*)d_in[4];
    const float* W_inner   = (const float*)d_in[5];
    const float* b_inner   = (const float*)d_in[6];
    const float* W_n       = (const float*)d_in[7];
    const float* b_n       = (const float*)d_in[8];
    const float* W_out     = (const float*)d_in[9];
    const float* b_out     = (const float*)d_in[10];
    const float* pW1       = (const float*)d_in[11];
    const float* pb1       = (const float*)d_in[12];
    const float* pW2       = (const float*)d_in[13];
    const float* pb2       = (const float*)d_in[14];
    const float* gW1       = (const float*)d_in[15];
    const float* gb1       = (const float*)d_in[16];
    const float* gW2       = (const float*)d_in[17];
    const float* gb2       = (const float*)d_in[18];
    const float* fcEW1     = (const float*)d_in[19];
    const float* fcEW2     = (const float*)d_in[20];
    const float* fcW1      = (const float*)d_in[21];
    const float* fcb1      = (const float*)d_in[22];
    const float* fcW2      = (const float*)d_in[23];
    const float* fcb2      = (const float*)d_in[24];

    int N = in_sizes[0] / TOT;
    int E = in_sizes[2];
    int mt = (E + MT - 1) / MT;
    int nt = (N + MT - 1) / MT;

    void *p_s0f, *p_h, *p_w, *p_np, *p_g, *p_pwhi, *p_pwlo, *p_we_;
    void *p_xp, *p_nf, *p_nh, *p_ng, *p_na0, *p_na;
    cudaGetSymbolAddress(&p_s0f, g_s0f);
    cudaGetSymbolAddress(&p_h,   g_h);
    cudaGetSymbolAddress(&p_w,   g_w);
    cudaGetSymbolAddress(&p_np,  g_np);
    cudaGetSymbolAddress(&p_g,   g_g);
    cudaGetSymbolAddress(&p_pwhi, g_pw_hi);
    cudaGetSymbolAddress(&p_pwlo, g_pw_lo);
    cudaGetSymbolAddress(&p_xp,  g_xp);
    cudaGetSymbolAddress(&p_nf,  g_nf);
    cudaGetSymbolAddress(&p_nh,  g_nh);
    cudaGetSymbolAddress(&p_ng,  g_ng);
    cudaGetSymbolAddress(&p_na0, g_na0);
    cudaGetSymbolAddress(&p_na,  g_na);
    cudaGetSymbolAddress(&p_we_, g_we);
    const __nv_bfloat16* pwhi = (const __nv_bfloat16*)p_pwhi;
    const __nv_bfloat16* pwlo = (const __nv_bfloat16*)p_pwlo;

    cudaFuncSetAttribute(gemm_kernel, cudaFuncAttributeMaxDynamicSharedMemorySize, SM_TOTAL);

    // L0: ALL weight prep in one launch
    prep_all<<<dim3((NM * NM + 255) / 256, 15), 256>>>(
        fcW1, fcW2, gW1, gW2, pW1, pW2, W_out, W_inner, W_n);

    k_xplan<<<(N * MUL + 255) / 256, 256>>>(node_attr, N);
    k_mtwe<<<(E + 1) / 2, 256>>>(edge_attr, fcEW1, fcEW2, E);

    // L3: na0 = irrep(xp, W_inner)
    gemm_kernel<<<dim3(nt, 9), GT, SM_TOTAL>>>(
        (const float*)p_xp, TOT, 2, pwhi + OFF_WIN, pwlo + OFF_WIN,
        (float*)p_na0, TOT, b_inner, nullptr, nullptr, nullptr, nullptr, 2, 4, N);

    // L4: nh = silu(nf @ pW1 + pb1)
    gemm_kernel<<<dim3(nt, 3), GT, SM_TOTAL>>>(
        (const float*)p_nf, NM, 6, pwhi + OFF_PW1, pwlo + OFF_PW1,
        (float*)p_nh, NM, pb1, nullptr, nullptr, nullptr, nullptr, 0, 1, N);

    // L5: ng = nh @ pW2 + pb2
    gemm_kernel<<<dim3(nt, 3), GT, SM_TOTAL>>>(
        (const float*)p_nh, NM, 6, pwhi + OFF_PW2, pwlo + OFF_PW2,
        (float*)p_ng, NM, pb2, nullptr, nullptr, nullptr, nullptr, 0, 0, N);

    k_gate_node<<<(N * MUL + 255) / 256, 256>>>(N);

    // L6: na = irrep(gated xp, W_n)
    gemm_kernel<<<dim3(nt, 9), GT, SM_TOTAL>>>(
        (const float*)p_xp, TOT, 2, pwhi + OFF_WN, pwlo + OFF_WN,
        (float*)p_na, TOT, b_n, nullptr, nullptr, nullptr, nullptr, 2, 4, N);

    // ---- edge stage ----
    // G1: h1 = silu(s0 @ fcW1 + fcb1), s0 computed in A-load from g_na0
    gemm_kernel<<<dim3(mt, 1), GT, SM_TOTAL>>>(
        (const float*)p_na0, TOT, 6, pwhi + OFF_FCW1, pwlo + OFF_FCW1,
        (float*)p_h, MUL, fcb1, nullptr, nullptr, dst, src, 3, 1, E);

    // G2: w = (h1 @ fcW2 + fcb2) * we
    gemm_kernel<<<dim3(mt, 1), GT, SM_TOTAL>>>(
        (const float*)p_h, MUL, 2, pwhi + OFF_FCW2, pwlo + OFF_FCW2,
        (float*)p_w, MUL, fcb2, (const float*)p_we_, nullptr, nullptr, nullptr, 0, 2, E);

    // f0'
    k_f0<<<(E * MUL + 255) / 256, 256>>>(dst, src, E);

    // G3: h = silu(f0' @ ngW1 + ngb1)
    gemm_kernel<<<dim3(mt, 3), GT, SM_TOTAL>>>(
        (const float*)p_s0f, NM, 6, pwhi + OFF_NGW1, pwlo + OFF_NGW1,
        (float*)p_h, NM, gb1, nullptr, nullptr, nullptr, nullptr, 0, 1, E);

    // G4: g = h @ ngW2 + ngb2
    gemm_kernel<<<dim3(mt, 3), GT, SM_TOTAL>>>(
        (const float*)p_h, NM, 6, pwhi + OFF_NGW2, pwlo + OFF_NGW2,
        (float*)p_g, NM, gb2, nullptr, nullptr, nullptr, nullptr, 0, 0, E);

    // G5: planar out = irrep(gate(np, g), W_out)*S128 (+bias plane0); np recomputed
    gemm_kernel<<<dim3(mt, 9), GT, SM_TOTAL>>>(
        (const float*)p_na, TOT, 2, pwhi + OFF_WOUT, pwlo + OFF_WOUT,
        (float*)p_np, TOT, b_out, (const float*)p_w, (const float*)p_g, dst, src, 1, 4, E);

    // merge + npa
    k_out<<<(E * (TOT / 4) + 255) / 256, 256>>>(npa, (float*)d_out, E);
}

// round 17
// speedup vs baseline: 1.4084x; 1.0143x over previous
#include <cuda_runtime.h>
#include <cuda_bf16.h>
#include <cstdint>
#include <cstddef>

#define MUL 128
#define TOT 1152
#define NM  384
#define MAXN 4096
#define MAXE 65536
#define S128 0.08838834764831845f
#define IS3  0.57735026918962576f
#define IS5  0.44721359549995794f

// ---------------- scratch ----------------
__device__ float g_na0[MAXN * TOT];
__device__ float g_na [MAXN * TOT];
__device__ float g_xp [MAXN * TOT];
__device__ float g_nf [MAXN * NM];
__device__ float g_nh [MAXN * NM];
__device__ float g_ng [MAXN * NM];
__device__ float g_s0f[(size_t)MAXE * NM];   // f0'
__device__ float g_we [(size_t)MAXE * MUL];
__device__ float g_h  [(size_t)MAXE * NM];
__device__ float g_w  [(size_t)MAXE * MUL];
__device__ float g_np [(size_t)MAXE * TOT];
__device__ float g_g  [(size_t)MAXE * NM];

#define BLK 8192
#define OFF_FCW1 0
#define OFF_FCW2 49152
#define OFF_NGW1 65536
#define OFF_NGW2 212992
#define OFF_WOUT 360448
#define OFF_WIN  409600
#define OFF_WN   458752
#define OFF_PW1  507904
#define OFF_PW2  655360
#define PW_TOTAL 802816
__device__ __nv_bfloat16 g_pw_hi[PW_TOTAL];
__device__ __nv_bfloat16 g_pw_lo[PW_TOTAL];

__device__ __forceinline__ uint32_t smem_to_u32(const void* p) {
    uint32_t a;
    asm("{ .reg .u64 t; cvta.to.shared.u64 t, %1; cvt.u32.u64 %0, t; }" : "=r"(a) : "l"(p));
    return a;
}
__device__ __forceinline__ float silu_f(float x) { return x / (1.0f + __expf(-x)); }
__device__ __forceinline__ float ssp_f(float x) {
    return fmaxf(x, 0.0f) + log1pf(__expf(-fabsf(x))) - 0.69314718055994531f;
}
__device__ __forceinline__ int sw_unit(int row, int u) {
    return row * 8 + (u ^ (row & 7));
}
__device__ __forceinline__ int merged_to_planar(int j) {
    if (j < 128) return j;
    if (j < 512) { int r = j - 128; int u = r / 3; int c = r - 3 * u; return (1 + c) * 128 + u; }
    int r = j - 512; int u = r / 5; int c = r - 5 * u; return (4 + c) * 128 + u;
}

__device__ __forceinline__ void ldmat_x4(uint32_t* r, uint32_t addr) {
    asm volatile("ldmatrix.sync.aligned.m8n8.x4.shared.b16 {%0,%1,%2,%3}, [%4];"
        : "=r"(r[0]), "=r"(r[1]), "=r"(r[2]), "=r"(r[3]) : "r"(addr));
}
__device__ __forceinline__ void mma_bf16(float* c, const uint32_t* a, uint32_t b0, uint32_t b1) {
    asm volatile("mma.sync.aligned.m16n8k16.row.col.f32.bf16.bf16.f32 "
        "{%0,%1,%2,%3}, {%4,%5,%6,%7}, {%8,%9}, {%0,%1,%2,%3};"
        : "+f"(c[0]), "+f"(c[1]), "+f"(c[2]), "+f"(c[3])
        : "r"(a[0]), "r"(a[1]), "r"(a[2]), "r"(a[3]), "r"(b0), "r"(b1));
}
__device__ __forceinline__ void cp_async16(uint32_t dst, const void* src) {
    asm volatile("cp.async.cg.shared.global [%0], [%1], 16;" :: "r"(dst), "l"(src));
}
#define CP_COMMIT() asm volatile("cp.async.commit_group;" ::: "memory")
#define CP_WAIT0()  asm volatile("cp.async.wait_group 0;" ::: "memory")

// ---------------- batched weight prep ----------------
__global__ void prep_all(
    const float* __restrict__ fcW1, const float* __restrict__ fcW2,
    const float* __restrict__ gW1,  const float* __restrict__ gW2,
    const float* __restrict__ pW1,  const float* __restrict__ pW2,
    const float* __restrict__ Wout, const float* __restrict__ Win,
    const float* __restrict__ Wn)
{
    int job = blockIdx.y;
    const float* W;
    int K, Nn, off;
    switch (job) {
        case 0:  W = fcW1; K = NM;  Nn = MUL; off = OFF_FCW1; break;
        case 1:  W = fcW2; K = MUL; Nn = MUL; off = OFF_FCW2; break;
        case 2:  W = gW1;  K = NM;  Nn = NM;  off = OFF_NGW1; break;
        case 3:  W = gW2;  K = NM;  Nn = NM;  off = OFF_NGW2; break;
        case 4:  W = pW1;  K = NM;  Nn = NM;  off = OFF_PW1;  break;
        case 5:  W = pW2;  K = NM;  Nn = NM;  off = OFF_PW2;  break;
        default: {
            int grp = (job - 6) / 3;
            int i   = (job - 6) % 3;
            const float* base = (grp == 0) ? Wout : (grp == 1) ? Win : Wn;
            int boff = (grp == 0) ? OFF_WOUT : (grp == 1) ? OFF_WIN : OFF_WN;
            W = base + i * MUL * MUL; K = MUL; Nn = MUL; off = boff + i * 2 * BLK;
            break;
        }
    }
    int idx = blockIdx.x * blockDim.x + threadIdx.x;
    if (idx >= K * Nn) return;
    int kg = idx / Nn, ng = idx - kg * Nn;
    float x = W[idx];
    __nv_bfloat16 h = __float2bfloat16(x);
    __nv_bfloat16 l = __float2bfloat16(x - __bfloat162float(h));
    int kch = K >> 6;
    int nt = ng >> 7, n = ng & 127, kc = kg >> 6, k = kg & 63;
    int blk = nt * kch + kc;
    int e = blk * BLK + sw_unit(n, k >> 3) * 8 + (k & 7) + off;
    g_pw_hi[e] = h;
    g_pw_lo[e] = l;
}

// ---------------- elementwise kernels ----------------
__global__ void k_xplan(const float* __restrict__ na, int N) {
    int idx = blockIdx.x * blockDim.x + threadIdx.x;
    if (idx >= N * MUL) return;
    int n = idx >> 7, u = idx & 127;
    const float* x = na + (size_t)n * TOT;
    float v[9];
    v[0] = x[u];
    #pragma unroll
    for (int c = 0; c < 3; c++) v[1 + c] = x[128 + u * 3 + c];
    #pragma unroll
    for (int c = 0; c < 5; c++) v[4 + c] = x[512 + u * 5 + c];
    float* xp = g_xp + (size_t)n * TOT;
    #pragma unroll
    for (int p = 0; p < 9; p++) xp[p * 128 + u] = v[p];
    float* f = g_nf + (size_t)n * NM;
    f[u] = v[0];
    f[128 + u] = sqrtf(v[1] * v[1] + v[2] * v[2] + v[3] * v[3]);
    f[256 + u] = sqrtf(v[4] * v[4] + v[5] * v[5] + v[6] * v[6] + v[7] * v[7] + v[8] * v[8]);
}

__global__ void k_gate_node(int N) {
    int idx = blockIdx.x * blockDim.x + threadIdx.x;
    if (idx >= N * MUL) return;
    int n = idx >> 7, u = idx & 127;
    const float* g = g_ng + (size_t)n * NM;
    float* xp = g_xp + (size_t)n * TOT;
    float g1 = g[128 + u], g2 = g[256 + u];
    xp[u] = g[u];
    #pragma unroll
    for (int p = 1; p < 4; p++) xp[p * 128 + u] *= g1;
    #pragma unroll
    for (int p = 4; p < 9; p++) xp[p * 128 + u] *= g2;
}

__global__ void k_mtwe(const float* __restrict__ ea,
                       const float* __restrict__ W1, const float* __restrict__ W2, int E) {
    __shared__ float smt[2][8];
    int half = threadIdx.x >> 7;
    int t = threadIdx.x & 127;
    int e = blockIdx.x * 2 + half;
    int ec = (e < E) ? e : (E - 1);
    if (t < 8) {
        const float* a = ea + (size_t)ec * 64;
        float acc = 0.0f;
        #pragma unroll 16
        for (int i = 0; i < 64; i++) acc += a[i] * W1[i * 8 + t];
        smt[half][t] = ssp_f(acc * 0.125f);
    }
    __syncthreads();
    if (e < E) {
        float acc = 0.0f;
        #pragma unroll
        for (int j = 0; j < 8; j++) acc += smt[half][j] * W2[j * MUL + t];
        g_we[(size_t)e * MUL + t] = acc * 0.35355339059327373f;
    }
}

__global__ void k_f0(const int* __restrict__ dst, const int* __restrict__ src, int E) {
    int idx = blockIdx.x * blockDim.x + threadIdx.x;
    if (idx >= E * MUL) return;
    int e = idx >> 7, u = idx & 127;
    const float* ns = g_na + (size_t)src[e] * TOT;
    const float* nd = g_na + (size_t)dst[e] * TOT;
    const float* w = g_w + (size_t)e * MUL;
    float np[9];
    np[0] = (ns[u] + nd[u]) * w[u / 9];
    #pragma unroll
    for (int p = 1; p < 4; p++) {
        int j = 128 + u * 3 + (p - 1);
        np[p] = (ns[p * 128 + u] + nd[p * 128 + u]) * w[j / 9];
    }
    #pragma unroll
    for (int p = 4; p < 9; p++) {
        int j = 512 + u * 5 + (p - 4);
        np[p] = (ns[p * 128 + u] + nd[p * 128 + u]) * w[j / 9];
    }
    float* f = g_s0f + (size_t)e * NM;
    f[u] = np[0];
    f[128 + u] = sqrtf(np[1] * np[1] + np[2] * np[2] + np[3] * np[3]);
    f[256 + u] = sqrtf(np[4] * np[4] + np[5] * np[5] + np[6] * np[6]
                     + np[7] * np[7] + np[8] * np[8]);
}

__global__ void k_out(const float* __restrict__ npa, float* __restrict__ out, int E) {
    int idx = blockIdx.x * blockDim.x + threadIdx.x;
    if (idx >= E * (TOT / 4)) return;
    int e = idx / (TOT / 4);
    int j4 = (idx - e * (TOT / 4)) * 4;
    const float* pl = g_np + (size_t)e * TOT;
    float4 npv = *(const float4*)(npa + (size_t)e * TOT + j4);
    float4 o;
    o.x = pl[merged_to_planar(j4)]     + npv.x;
    o.y = pl[merged_to_planar(j4 + 1)] + npv.y;
    o.z = pl[merged_to_planar(j4 + 2)] + npv.z;
    o.w = pl[merged_to_planar(j4 + 3)] + npv.w;
    *(float4*)(out + (size_t)e * TOT + j4) = o;
}

// ---------------- mma.sync GEMM: 64x128 tile, 3 CTAs/SM ----------------
// 8 warps as 2m x 4n, warp tile 32x32, acc 32 regs/thread.
#define GT 256
#define MT 64
#define SM_AHI 0
#define SM_ALO 8192
#define SM_BHI 16384
#define SM_BLO 32768
#define SM_IDX 49152
#define SM_TOTAL 49664

// mode_a: 0 plain; 1 G5 np recompute (plane=by); 2 planar plain (plane=by); 3 G1 s0
// mode_ep: 0 +bias ; 1 silu(+bias) ; 2 (acc+bias)*mul ; 4 planar *S128 (+bias if plane0)
__global__ void __launch_bounds__(GT, 3) gemm_kernel(
    const float* __restrict__ A, int lda, int kchunks,
    const __nv_bfloat16* __restrict__ Bhi, const __nv_bfloat16* __restrict__ Blo,
    float* __restrict__ OUT, int ldo,
    const float* __restrict__ bias,
    const float* __restrict__ mul,
    const float* __restrict__ gate,
    const int* __restrict__ dstp, const int* __restrict__ srcp,
    int mode_a, int mode_ep, int E)
{
    extern __shared__ char smg[];
    uint32_t smb = smem_to_u32(smg);
    int* SIDX = (int*)(smg + SM_IDX);
    const int tid = threadIdx.x;
    const int wid = tid >> 5;
    const int lane = tid & 31;
    const int m0 = blockIdx.x * MT;
    const int by = blockIdx.y;
    const int plane = (mode_a == 1 || mode_a == 2) ? by : 0;
    const int ntb = (mode_a == 1 || mode_a == 2) ? 0 : by;

    const int wm0 = (wid & 1) * 32;       // 2 m-warps
    const int wn0 = (wid >> 1) * 32;      // 4 n-warps

    if (mode_a == 1 || mode_a == 3) {
        if (tid < MT) {
            int e = m0 + tid; if (e >= E) e = E - 1;
            SIDX[tid] = dstp[e];
            SIDX[MT + tid] = srcp[e];
        }
        __syncthreads();
    }

    float acc[2][4][4];
    #pragma unroll
    for (int i = 0; i < 2; i++)
        #pragma unroll
        for (int j = 0; j < 4; j++)
            #pragma unroll
            for (int q = 0; q < 4; q++) acc[i][j][q] = 0.0f;

    int bsel = ntb;
    if (mode_a == 1 || mode_a == 2) bsel = (plane == 0) ? 0 : (plane < 4 ? 1 : 2);

    for (int kc = 0; kc < kchunks; kc++) {
        // B tile via cp.async.cg (overlaps A convert below)
        {
            int blk = bsel * kchunks + kc;
            const char* sH = (const char*)(Bhi + (size_t)blk * BLK);
            const char* sL = (const char*)(Blo + (size_t)blk * BLK);
            #pragma unroll
            for (int it = 0; it < 4; it++) {
                int i = tid + it * GT;
                cp_async16(smb + SM_BHI + i * 16, sH + i * 16);
                cp_async16(smb + SM_BLO + i * 16, sL + i * 16);
            }
            CP_COMMIT();
        }
        // A tile: 64 rows x 64 k = 512 units, 2 per thread
        #pragma unroll
        for (int it = 0; it < 2; it++) {
            int i = tid + it * GT;
            int r = i >> 3, u = i & 7;
            int e = m0 + r;
            int k0 = u * 8;
            float v[8];
            #pragma unroll
            for (int q = 0; q < 8; q++) v[q] = 0.0f;
            if (e < E) {
                if (mode_a == 0) {
                    const float* p = A + (size_t)e * lda + kc * 64 + k0;
                    float4 v0 = *(const float4*)(p);
                    float4 v1 = *(const float4*)(p + 4);
                    v[0]=v0.x; v[1]=v0.y; v[2]=v0.z; v[3]=v0.w;
                    v[4]=v1.x; v[5]=v1.y; v[6]=v1.z; v[7]=v1.w;
                } else if (mode_a == 2) {
                    const float* p = A + (size_t)e * lda + plane * 128 + kc * 64 + k0;
                    float4 v0 = *(const float4*)(p);
                    float4 v1 = *(const float4*)(p + 4);
                    v[0]=v0.x; v[1]=v0.y; v[2]=v0.z; v[3]=v0.w;
                    v[4]=v1.x; v[5]=v1.y; v[6]=v1.z; v[7]=v1.w;
                } else if (mode_a == 1) {
                    if (plane == 0) {
                        const float* p = gate + (size_t)e * NM + kc * 64 + k0;
                        float4 v0 = *(const float4*)(p);
                        float4 v1 = *(const float4*)(p + 4);
                        v[0]=v0.x; v[1]=v0.y; v[2]=v0.z; v[3]=v0.w;
                        v[4]=v1.x; v[5]=v1.y; v[6]=v1.z; v[7]=v1.w;
                    } else {
                        const float* nd = A + (size_t)SIDX[r] * TOT + plane * 128 + kc * 64 + k0;
                        const float* ns = A + (size_t)SIDX[MT + r] * TOT + plane * 128 + kc * 64 + k0;
                        int go = (plane < 4) ? 128 : 256;
                        const float* gp = gate + (size_t)e * NM + go + kc * 64 + k0;
                        const float* wr = mul + (size_t)e * MUL;
                        #pragma unroll
                        for (int q = 0; q < 8; q++) {
                            int k = kc * 64 + k0 + q;
                            int j = (plane < 4) ? (128 + k * 3 + (plane - 1))
                                                : (512 + k * 5 + (plane - 4));
                            v[q] = (nd[q] + ns[q]) * wr[j / 9] * gp[q];
                        }
                    }
                } else { // mode_a == 3: s0 from g_na0 gathers
                    const float* nd = A + (size_t)SIDX[r] * TOT;
                    const float* ns = A + (size_t)SIDX[MT + r] * TOT;
                    int kg = kc * 64 + k0;
                    if (kg < 128) {
                        #pragma unroll
                        for (int q = 0; q < 8; q++)
                            v[q] = 0.5f * (nd[kg + q] + ns[kg + q]);
                    } else if (kg < 256) {
                        int u0 = kg - 128;
                        #pragma unroll
                        for (int q = 0; q < 8; q++) {
                            int uu = u0 + q;
                            v[q] = (nd[128 + uu] * ns[128 + uu] + nd[256 + uu] * ns[256 + uu]
                                  + nd[384 + uu] * ns[384 + uu]) * IS3;
                        }
                    } else {
                        int u0 = kg - 256;
                        #pragma unroll
                        for (int q = 0; q < 8; q++) {
                            int uu = u0 + q;
                            v[q] = (nd[512 + uu] * ns[512 + uu] + nd[640 + uu] * ns[640 + uu]
                                  + nd[768 + uu] * ns[768 + uu] + nd[896 + uu] * ns[896 + uu]
                                  + nd[1024 + uu] * ns[1024 + uu]) * IS5;
                        }
                    }
                }
            }
            uint32_t hi[4], lo[4];
            #pragma unroll
            for (int q = 0; q < 4; q++) {
                __nv_bfloat16 h0 = __float2bfloat16(v[2*q]);
                __nv_bfloat16 h1 = __float2bfloat16(v[2*q+1]);
                __nv_bfloat16 l0 = __float2bfloat16(v[2*q]   - __bfloat162float(h0));
                __nv_bfloat16 l1 = __float2bfloat16(v[2*q+1] - __bfloat162float(h1));
                __nv_bfloat162 h2(h0, h1), l2(l0, l1);
                hi[q] = *(uint32_t*)&h2;
                lo[q] = *(uint32_t*)&l2;
            }
            int off = sw_unit(r, u) * 16;
            *(uint4*)(smg + SM_AHI + off) = make_uint4(hi[0], hi[1], hi[2], hi[3]);
            *(uint4*)(smg + SM_ALO + off) = make_uint4(lo[0], lo[1], lo[2], lo[3]);
        }
        CP_WAIT0();
        __syncthreads();

        // MMA with cross-pass fragment reuse (8 ldmatrix.x4 per ks)
        #pragma unroll
        for (int ks = 0; ks < 4; ks++) {
            const int ua = ks * 2 + (lane >> 4);
            const int ub = ks * 2 + ((lane >> 3) & 1);
            const int rowa0 = wm0 + (lane & 15);
            const int nb = wn0 + (lane >> 4) * 8 + (lane & 7);

            uint32_t aH[2][4];
            #pragma unroll
            for (int mt2 = 0; mt2 < 2; mt2++)
                ldmat_x4(aH[mt2], smb + SM_AHI + sw_unit(rowa0 + mt2 * 16, ua) * 16);
            uint32_t bH[2][4];
            #pragma unroll
            for (int nq = 0; nq < 2; nq++)
                ldmat_x4(bH[nq], smb + SM_BHI + sw_unit(nb + nq * 16, ub) * 16);
            #pragma unroll
            for (int mt2 = 0; mt2 < 2; mt2++)
                #pragma unroll
                for (int nt2 = 0; nt2 < 4; nt2++)
                    mma_bf16(acc[mt2][nt2], aH[mt2], bH[nt2 >> 1][(nt2 & 1) * 2],
                             bH[nt2 >> 1][(nt2 & 1) * 2 + 1]);
            {
                uint32_t aL[2][4];
                #pragma unroll
                for (int mt2 = 0; mt2 < 2; mt2++)
                    ldmat_x4(aL[mt2], smb + SM_ALO + sw_unit(rowa0 + mt2 * 16, ua) * 16);
                #pragma unroll
                for (int mt2 = 0; mt2 < 2; mt2++)
                    #pragma unroll
                    for (int nt2 = 0; nt2 < 4; nt2++)
                        mma_bf16(acc[mt2][nt2], aL[mt2], bH[nt2 >> 1][(nt2 & 1) * 2],
                                 bH[nt2 >> 1][(nt2 & 1) * 2 + 1]);
            }
            {
                uint32_t bL[2][4];
                #pragma unroll
                for (int nq = 0; nq < 2; nq++)
                    ldmat_x4(bL[nq], smb + SM_BLO + sw_unit(nb + nq * 16, ub) * 16);
                #pragma unroll
                for (int mt2 = 0; mt2 < 2; mt2++)
                    #pragma unroll
                    for (int nt2 = 0; nt2 < 4; nt2++)
                        mma_bf16(acc[mt2][nt2], aH[mt2], bL[nt2 >> 1][(nt2 & 1) * 2],
                                 bL[nt2 >> 1][(nt2 & 1) * 2 + 1]);
            }
        }
        __syncthreads();
    }

    // ---------------- epilogue (paired float2 loads + stores) ----------------
    const int qr = lane >> 2;
    const int qc = (lane & 3) * 2;
    #pragma unroll
    for (int mt2 = 0; mt2 < 2; mt2++) {
        #pragma unroll
        for (int nt2 = 0; nt2 < 4; nt2++) {
            int cl = wn0 + nt2 * 8 + qc;
            float* c = acc[mt2][nt2];
            // per-column operands hoisted out of the row loop
            float2 bv = make_float2(0.f, 0.f);
            if (mode_ep == 4) {
                if (plane == 0 && bias) bv = *(const float2*)(bias + cl);
            } else if (bias) {
                bv = *(const float2*)(bias + ntb * 128 + cl);
            }
            #pragma unroll
            for (int rr = 0; rr < 2; rr++) {
                int e = m0 + wm0 + mt2 * 16 + qr + rr * 8;
                if (e >= E) continue;
                float v0 = c[rr * 2], v1 = c[rr * 2 + 1];
                if (mode_ep == 4) {
                    v0 = v0 * S128 + bv.x;
                    v1 = v1 * S128 + bv.y;
                    int n = plane * 128 + cl;
                    *(float2*)(OUT + (size_t)e * ldo + n) = make_float2(v0, v1);
                } else {
                    int n = ntb * 128 + cl;
                    v0 += bv.x; v1 += bv.y;
                    if (mode_ep == 1) { v0 = silu_f(v0); v1 = silu_f(v1); }
                    else if (mode_ep == 2) {
                        float2 mv = *(const float2*)(mul + (size_t)e * MUL + cl);
                        v0 *= mv.x;
                        v1 *= mv.y;
                    }
                    *(float2*)(OUT + (size_t)e * ldo + n) = make_float2(v0, v1);
                }
            }
        }
    }
}

// ---------------- launch ----------------
extern "C" void kernel_launch(void* const* d_in, const int* in_sizes, int n_in,
                              void* d_out, int out_size) {
    const float* node_attr = (const float*)d_in[0];
    const float* edge_attr = (const float*)d_in[1];
    const int*   dst       = (const int*)d_in[2];
    const int*   src       = (const int*)d_in[3];
    const float* npa       = (const float*)d_in[4];
    const float* W_inner   = (const float*)d_in[5];
    const float* b_inner   = (const float*)d_in[6];
    const float* W_n       = (const float*)d_in[7];
    const float* b_n       = (const float*)d_in[8];
    const float* W_out     = (const float*)d_in[9];
    const float* b_out     = (const float*)d_in[10];
    const float* pW1       = (const float*)d_in[11];
    const float* pb1       = (const float*)d_in[12];
    const float* pW2       = (const float*)d_in[13];
    const float* pb2       = (const float*)d_in[14];
    const float* gW1       = (const float*)d_in[15];
    const float* gb1       = (const float*)d_in[16];
    const float* gW2       = (const float*)d_in[17];
    const float* gb2       = (const float*)d_in[18];
    const float* fcEW1     = (const float*)d_in[19];
    const float* fcEW2     = (const float*)d_in[20];
    const float* fcW1      = (const float*)d_in[21];
    const float* fcb1      = (const float*)d_in[22];
    const float* fcW2      = (const float*)d_in[23];
    const float* fcb2      = (const float*)d_in[24];

    int N = in_sizes[0] / TOT;
    int E = in_sizes[2];
    int mt = (E + MT - 1) / MT;
    int nt = (N + MT - 1) / MT;

    void *p_s0f, *p_h, *p_w, *p_np, *p_g, *p_pwhi, *p_pwlo, *p_we_;
    void *p_xp, *p_nf, *p_nh, *p_ng, *p_na0, *p_na;
    cudaGetSymbolAddress(&p_s0f, g_s0f);
    cudaGetSymbolAddress(&p_h,   g_h);
    cudaGetSymbolAddress(&p_w,   g_w);
    cudaGetSymbolAddress(&p_np,  g_np);
    cudaGetSymbolAddress(&p_g,   g_g);
    cudaGetSymbolAddress(&p_pwhi, g_pw_hi);
    cudaGetSymbolAddress(&p_pwlo, g_pw_lo);
    cudaGetSymbolAddress(&p_xp,  g_xp);
    cudaGetSymbolAddress(&p_nf,  g_nf);
    cudaGetSymbolAddress(&p_nh,  g_nh);
    cudaGetSymbolAddress(&p_ng,  g_ng);
    cudaGetSymbolAddress(&p_na0, g_na0);
    cudaGetSymbolAddress(&p_na,  g_na);
    cudaGetSymbolAddress(&p_we_, g_we);
    const __nv_bfloat16* pwhi = (const __nv_bfloat16*)p_pwhi;
    const __nv_bfloat16* pwlo = (const __nv_bfloat16*)p_pwlo;

    cudaFuncSetAttribute(gemm_kernel, cudaFuncAttributeMaxDynamicSharedMemorySize, SM_TOTAL);

    // L0: ALL weight prep in one launch
    prep_all<<<dim3((NM * NM + 255) / 256, 15), 256>>>(
        fcW1, fcW2, gW1, gW2, pW1, pW2, W_out, W_inner, W_n);

    k_xplan<<<(N * MUL + 255) / 256, 256>>>(node_attr, N);
    k_mtwe<<<(E + 1) / 2, 256>>>(edge_attr, fcEW1, fcEW2, E);

    // L3: na0 = irrep(xp, W_inner)
    gemm_kernel<<<dim3(nt, 9), GT, SM_TOTAL>>>(
        (const float*)p_xp, TOT, 2, pwhi + OFF_WIN, pwlo + OFF_WIN,
        (float*)p_na0, TOT, b_inner, nullptr, nullptr, nullptr, nullptr, 2, 4, N);

    // L4: nh = silu(nf @ pW1 + pb1)
    gemm_kernel<<<dim3(nt, 3), GT, SM_TOTAL>>>(
        (const float*)p_nf, NM, 6, pwhi + OFF_PW1, pwlo + OFF_PW1,
        (float*)p_nh, NM, pb1, nullptr, nullptr, nullptr, nullptr, 0, 1, N);

    // L5: ng = nh @ pW2 + pb2
    gemm_kernel<<<dim3(nt, 3), GT, SM_TOTAL>>>(
        (const float*)p_nh, NM, 6, pwhi + OFF_PW2, pwlo + OFF_PW2,
        (float*)p_ng, NM, pb2, nullptr, nullptr, nullptr, nullptr, 0, 0, N);

    k_gate_node<<<(N * MUL + 255) / 256, 256>>>(N);

    // L6: na = irrep(gated xp, W_n)
    gemm_kernel<<<dim3(nt, 9), GT, SM_TOTAL>>>(
        (const float*)p_xp, TOT, 2, pwhi + OFF_WN, pwlo + OFF_WN,
        (float*)p_na, TOT, b_n, nullptr, nullptr, nullptr, nullptr, 2, 4, N);

    // ---- edge stage ----
    // G1: h1 = silu(s0 @ fcW1 + fcb1), s0 computed in A-load from g_na0
    gemm_kernel<<<dim3(mt, 1), GT, SM_TOTAL>>>(
        (const float*)p_na0, TOT, 6, pwhi + OFF_FCW1, pwlo + OFF_FCW1,
        (float*)p_h, MUL, fcb1, nullptr, nullptr, dst, src, 3, 1, E);

    // G2: w = (h1 @ fcW2 + fcb2) * we
    gemm_kernel<<<dim3(mt, 1), GT, SM_TOTAL>>>(
        (const float*)p_h, MUL, 2, pwhi + OFF_FCW2, pwlo + OFF_FCW2,
        (float*)p_w, MUL, fcb2, (const float*)p_we_, nullptr, nullptr, nullptr, 0, 2, E);

    // f0'
    k_f0<<<(E * MUL + 255) / 256, 256>>>(dst, src, E);

    // G3: h = silu(f0' @ ngW1 + ngb1)
    gemm_kernel<<<dim3(mt, 3), GT, SM_TOTAL>>>(
        (const float*)p_s0f, NM, 6, pwhi + OFF_NGW1, pwlo + OFF_NGW1,
        (float*)p_h, NM, gb1, nullptr, nullptr, nullptr, nullptr, 0, 1, E);

    // G4: g = h @ ngW2 + ngb2
    gemm_kernel<<<dim3(mt, 3), GT, SM_TOTAL>>>(
        (const float*)p_h, NM, 6, pwhi + OFF_NGW2, pwlo + OFF_NGW2,
        (float*)p_g, NM, gb2, nullptr, nullptr, nullptr, nullptr, 0, 0, E);

    // G5: planar out = irrep(gate(np, g), W_out)*S128 (+bias plane0); np recomputed
    gemm_kernel<<<dim3(mt, 9), GT, SM_TOTAL>>>(
        (const float*)p_na, TOT, 2, pwhi + OFF_WOUT, pwlo + OFF_WOUT,
        (float*)p_np, TOT, b_out, (const float*)p_w, (const float*)p_g, dst, src, 1, 4, E);

    // merge + npa
    k_out<<<(E * (TOT / 4) + 255) / 256, 256>>>(npa, (float*)d_out, E);
}